// round 1
// baseline (speedup 1.0000x reference)
#include <cuda_runtime.h>
#include <cmath>

// Problem constants
#define L_SEQ  32768
#define DM     256            // d_model
#define DH     256            // d_hidden
#define NW1    512            // stacked re|im width
#define CHUNK  128
#define NCHUNK (L_SEQ / CHUNK)   // 256

typedef unsigned long long ull;

// ---------------- scratch (static device memory: allowed) ----------------
__device__ float  g_W1[DM * NW1];        // [m][j]  j<256: Bre*gamma col h ; j>=256: Bim*gamma
__device__ float  g_W2[NW1 * DM];        // [k][m]  k<256: C_re[m][k] ; k>=256: -C_im[m][k-256]
__device__ float2 g_lam[DH];
__device__ float2 g_lamT[DH];            // lambda^CHUNK (computed in double)
__device__ float  g_Bu[(size_t)L_SEQ * NW1];   // Bu, later overwritten in-place with h (64 MB)
__device__ float2 g_carry[NCHUNK * DH];
__device__ float2 g_hinit[NCHUNK * DH];

// ---------------- setup ----------------
__global__ void setup_params(const float* __restrict__ nu_log,
                             const float* __restrict__ theta_log) {
    int h = threadIdx.x;
    double nu = exp((double)nu_log[h]);
    double th = exp((double)theta_log[h]);
    double r  = exp(-nu);
    g_lam[h]  = make_float2((float)(r * cos(th)), (float)(r * sin(th)));
    double rT = exp(-(double)CHUNK * nu);
    double aT = (double)CHUNK * th;
    g_lamT[h] = make_float2((float)(rT * cos(aT)), (float)(rT * sin(aT)));
}

__global__ void setup_weights(const float* __restrict__ gamma_log,
                              const float* __restrict__ B_re,
                              const float* __restrict__ B_im,
                              const float* __restrict__ C_re,
                              const float* __restrict__ C_im) {
    int h = blockIdx.x;    // 0..255 (hidden index)
    int m = threadIdx.x;   // 0..255 (model index)
    float gma = expf(gamma_log[h]);
    g_W1[m * NW1 + h]        = B_re[h * DM + m] * gma;
    g_W1[m * NW1 + DH + h]   = B_im[h * DM + m] * gma;
    g_W2[h * DM + m]         = C_re[m * DH + h];
    g_W2[(DH + h) * DM + m]  = -C_im[m * DH + h];
}

// ---------------- fp32x2 packed FMA ----------------
__device__ __forceinline__ void ffma2(ull& d, ull a, ull b) {
    asm("fma.rn.f32x2 %0, %1, %2, %0;" : "+l"(d) : "l"(a), "l"(b));
}

// ---------------- tiled SGEMM body (128x128 tile, K-step 16, 256 thr, 8x8/thr) ---
// A: [Lrows x K] row-major, Bm: [K x N] row-major, Cm: [Lrows x N].
// EPI adds X[row][col]*Dv[col] (only valid when N == DM).
template<int N, int K, bool EPI>
__device__ __forceinline__ void sgemm_body(
    const float* __restrict__ A, const float* __restrict__ Bm,
    float* __restrict__ Cm,
    const float* __restrict__ X, const float* __restrict__ Dv)
{
    __shared__ float2 As2[16][128];   // duplicated-A: {a,a}
    __shared__ float  Bs[16][128];

    const int tid = threadIdx.x;
    const int tx  = tid & 15;            // col group
    const int ty  = tid >> 4;            // row group
    const int r0  = ty * 8;
    const int c0  = tx * 8;
    const int rowbase = blockIdx.y * 128;
    const int colbase = blockIdx.x * 128;

    // staging indices (each thread loads 8 contiguous A floats and 8 contiguous B floats)
    const int arow = tid >> 1;           // 0..127
    const int akq  = (tid & 1) * 8;      // 0 or 8 within the 16-wide k panel
    const int bk   = tid >> 4;           // 0..15
    const int bc   = (tid & 15) * 8;     // 0..120

    const float* Aptr = A  + (size_t)(rowbase + arow) * K + akq;
    const float* Bptr = Bm + (size_t)bk * N + colbase + bc;

    ull acc[8][4];
    #pragma unroll
    for (int i = 0; i < 8; i++)
        #pragma unroll
        for (int j = 0; j < 4; j++) acc[i][j] = 0ull;

    float4 ra0 = *(const float4*)(Aptr);
    float4 ra1 = *(const float4*)(Aptr + 4);
    float4 rb0 = *(const float4*)(Bptr);
    float4 rb1 = *(const float4*)(Bptr + 4);

    const int NS = K / 16;
    for (int s = 0; s < NS; s++) {
        __syncthreads();
        // store stage to smem
        {
            const float* va = (const float*)&ra0;
            #pragma unroll
            for (int j = 0; j < 4; j++) As2[akq + j][arow] = make_float2(va[j], va[j]);
            const float* vb = (const float*)&ra1;
            #pragma unroll
            for (int j = 0; j < 4; j++) As2[akq + 4 + j][arow] = make_float2(vb[j], vb[j]);
            *(float4*)&Bs[bk][bc]     = rb0;
            *(float4*)&Bs[bk][bc + 4] = rb1;
        }
        __syncthreads();
        if (s + 1 < NS) {  // prefetch next stage (overlaps with compute)
            ra0 = *(const float4*)(Aptr + (s + 1) * 16);
            ra1 = *(const float4*)(Aptr + (s + 1) * 16 + 4);
            rb0 = *(const float4*)(Bptr + (size_t)(s + 1) * 16 * N);
            rb1 = *(const float4*)(Bptr + (size_t)(s + 1) * 16 * N + 4);
        }
        #pragma unroll
        for (int k = 0; k < 16; k++) {
            ull a2[8];
            const ull* pa = (const ull*)&As2[k][r0];
            #pragma unroll
            for (int i = 0; i < 8; i++) a2[i] = pa[i];
            ull bp[4];
            const ull* pb = (const ull*)&Bs[k][c0];
            #pragma unroll
            for (int j = 0; j < 4; j++) bp[j] = pb[j];
            #pragma unroll
            for (int i = 0; i < 8; i++)
                #pragma unroll
                for (int j = 0; j < 4; j++)
                    ffma2(acc[i][j], a2[i], bp[j]);
        }
    }

    // epilogue
    #pragma unroll
    for (int i = 0; i < 8; i++) {
        int row = rowbase + r0 + i;
        float2 v0 = *(float2*)&acc[i][0];
        float2 v1 = *(float2*)&acc[i][1];
        float2 v2 = *(float2*)&acc[i][2];
        float2 v3 = *(float2*)&acc[i][3];
        float4 o0 = make_float4(v0.x, v0.y, v1.x, v1.y);
        float4 o1 = make_float4(v2.x, v2.y, v3.x, v3.y);
        int col = colbase + c0;
        if (EPI) {
            float4 x0 = *(const float4*)&X[(size_t)row * DM + col];
            float4 x1 = *(const float4*)&X[(size_t)row * DM + col + 4];
            float4 d0 = *(const float4*)&Dv[col];
            float4 d1 = *(const float4*)&Dv[col + 4];
            o0.x = fmaf(x0.x, d0.x, o0.x); o0.y = fmaf(x0.y, d0.y, o0.y);
            o0.z = fmaf(x0.z, d0.z, o0.z); o0.w = fmaf(x0.w, d0.w, o0.w);
            o1.x = fmaf(x1.x, d1.x, o1.x); o1.y = fmaf(x1.y, d1.y, o1.y);
            o1.z = fmaf(x1.z, d1.z, o1.z); o1.w = fmaf(x1.w, d1.w, o1.w);
        }
        *(float4*)&Cm[(size_t)row * N + col]     = o0;
        *(float4*)&Cm[(size_t)row * N + col + 4] = o1;
    }
}

// GEMM1: Bu[L x 512] = x[L x 256] @ W1[256 x 512]
__global__ __launch_bounds__(256, 2) void gemm1(const float* __restrict__ x) {
    sgemm_body<NW1, DM, false>(x, g_W1, g_Bu, nullptr, nullptr);
}

// GEMM2: y[L x 256] = h[L x 512] @ W2[512 x 256] + x * D
__global__ __launch_bounds__(256, 2) void gemm2(float* __restrict__ y,
                                                const float* __restrict__ x,
                                                const float* __restrict__ Dv) {
    sgemm_body<DM, NW1, true>(g_Bu, g_W2, y, x, Dv);
}

// ---------------- chunked scan ----------------
// Pass 1: per-chunk local scan with zero init -> chunk carry
__global__ void scan_carry() {
    int c  = blockIdx.x;
    int ch = threadIdx.x;
    float2 lam = g_lam[ch];
    float hr = 0.f, hi = 0.f;
    const float* base = g_Bu + (size_t)c * CHUNK * NW1;
    #pragma unroll 4
    for (int t = 0; t < CHUNK; t++) {
        float br = base[t * NW1 + ch];
        float bi = base[t * NW1 + DH + ch];
        float nr = fmaf(lam.x, hr, br);  nr = fmaf(-lam.y, hi, nr);
        float ni = fmaf(lam.x, hi, bi);  ni = fmaf( lam.y, hr, ni);
        hr = nr; hi = ni;
    }
    g_carry[c * DH + ch] = make_float2(hr, hi);
}

// Pass 2: sequential scan over chunks -> chunk-entry state
__global__ void chunk_prefix() {
    int ch = threadIdx.x;
    float2 lamT = g_lamT[ch];
    float hr = 0.f, hi = 0.f;
    #pragma unroll 4
    for (int c = 0; c < NCHUNK; c++) {
        g_hinit[c * DH + ch] = make_float2(hr, hi);
        float2 b = g_carry[c * DH + ch];
        float nr = fmaf(lamT.x, hr, b.x);  nr = fmaf(-lamT.y, hi, nr);
        float ni = fmaf(lamT.x, hi, b.y);  ni = fmaf( lamT.y, hr, ni);
        hr = nr; hi = ni;
    }
}

// Pass 3: per-chunk scan with correct init, overwrite Bu with h in-place
__global__ void scan_apply() {
    int c  = blockIdx.x;
    int ch = threadIdx.x;
    float2 lam = g_lam[ch];
    float2 h0  = g_hinit[c * DH + ch];
    float hr = h0.x, hi = h0.y;
    float* base = g_Bu + (size_t)c * CHUNK * NW1;
    #pragma unroll 4
    for (int t = 0; t < CHUNK; t++) {
        float br = base[t * NW1 + ch];
        float bi = base[t * NW1 + DH + ch];
        float nr = fmaf(lam.x, hr, br);  nr = fmaf(-lam.y, hi, nr);
        float ni = fmaf(lam.x, hi, bi);  ni = fmaf( lam.y, hr, ni);
        hr = nr; hi = ni;
        base[t * NW1 + ch]      = hr;
        base[t * NW1 + DH + ch] = hi;
    }
}

// ---------------- entry ----------------
extern "C" void kernel_launch(void* const* d_in, const int* in_sizes, int n_in,
                              void* d_out, int out_size) {
    const float* x         = (const float*)d_in[0];
    const float* nu_log    = (const float*)d_in[1];
    const float* theta_log = (const float*)d_in[2];
    const float* gamma_log = (const float*)d_in[3];
    const float* B_re      = (const float*)d_in[4];
    const float* B_im      = (const float*)d_in[5];
    const float* C_re      = (const float*)d_in[6];
    const float* C_im      = (const float*)d_in[7];
    const float* Dv        = (const float*)d_in[8];
    float* y = (float*)d_out;

    setup_params<<<1, 256>>>(nu_log, theta_log);
    setup_weights<<<256, 256>>>(gamma_log, B_re, B_im, C_re, C_im);

    gemm1<<<dim3(NW1 / 128, L_SEQ / 128), 256>>>(x);      // Bu = x @ W1
    scan_carry<<<NCHUNK, DH>>>();                          // per-chunk carries
    chunk_prefix<<<1, DH>>>();                             // chunk-entry states
    scan_apply<<<NCHUNK, DH>>>();                          // h (in-place over Bu)
    gemm2<<<dim3(DM / 128, L_SEQ / 128), 256>>>(y, x, Dv); // y = h @ W2 + x*D
}

// round 4
// speedup vs baseline: 1.7179x; 1.7179x over previous
#include <cuda_runtime.h>
#include <cuda_bf16.h>
#include <cmath>
#include <cstdint>

#define L_SEQ  32768
#define DM     256
#define DH     256
#define NW1    512
#define CHUNK  64
#define NCHUNK (L_SEQ / CHUNK)   // 512

// ---------------- scratch ----------------
__device__ float          g_Bu[(size_t)L_SEQ * NW1];          // GEMM1 out (fp32), scan input
__device__ __nv_bfloat16  g_xh[(size_t)L_SEQ * DM];
__device__ __nv_bfloat16  g_xl[(size_t)L_SEQ * DM];
__device__ __nv_bfloat16  g_hh[(size_t)L_SEQ * NW1];
__device__ __nv_bfloat16  g_hl[(size_t)L_SEQ * NW1];
__device__ __nv_bfloat16  g_W1h[NW1 * DM], g_W1l[NW1 * DM];   // W1T  [512][256]
__device__ __nv_bfloat16  g_W2h[DM * NW1], g_W2l[DM * NW1];   // W2T  [256][512]
__device__ float2         g_lam[DH];
__device__ float2         g_lamT[DH];
__device__ float2         g_carry[NCHUNK * DH];
__device__ float2         g_hinit[NCHUNK * DH];

// ---------------- PTX helpers (sm_80-compatible PTX: compiles at compute_103) --
__device__ __forceinline__ uint32_t smem_u32(const void* p) {
    uint32_t a;
    asm("{ .reg .u64 t; cvta.to.shared.u64 t, %1; cvt.u32.u64 %0, t; }" : "=r"(a) : "l"(p));
    return a;
}
__device__ __forceinline__ void cp16(uint32_t s, const void* g) {
    asm volatile("cp.async.cg.shared.global [%0], [%1], 16;" :: "r"(s), "l"(g));
}
__device__ __forceinline__ void cp_commit() {
    asm volatile("cp.async.commit_group;" ::: "memory");
}
__device__ __forceinline__ void ldsm4(uint32_t addr, uint32_t* r) {
    asm volatile("ldmatrix.sync.aligned.m8n8.x4.shared.b16 {%0,%1,%2,%3}, [%4];"
                 : "=r"(r[0]), "=r"(r[1]), "=r"(r[2]), "=r"(r[3]) : "r"(addr));
}
__device__ __forceinline__ void mma_bf16(float* c, const uint32_t* a, const uint32_t* b) {
    asm volatile("mma.sync.aligned.m16n8k16.row.col.f32.bf16.bf16.f32 "
                 "{%0,%1,%2,%3},{%4,%5,%6,%7},{%8,%9},{%0,%1,%2,%3};"
                 : "+f"(c[0]), "+f"(c[1]), "+f"(c[2]), "+f"(c[3])
                 : "r"(a[0]), "r"(a[1]), "r"(a[2]), "r"(a[3]), "r"(b[0]), "r"(b[1]));
}

// ---------------- setup ----------------
__global__ void setup_params(const float* __restrict__ nu_log,
                             const float* __restrict__ theta_log) {
    int h = threadIdx.x;
    double nu = exp((double)nu_log[h]);
    double th = exp((double)theta_log[h]);
    double r  = exp(-nu);
    g_lam[h]  = make_float2((float)(r * cos(th)), (float)(r * sin(th)));
    double rT = exp(-(double)CHUNK * nu);
    double aT = (double)CHUNK * th;
    g_lamT[h] = make_float2((float)(rT * cos(aT)), (float)(rT * sin(aT)));
}

__device__ __forceinline__ void split2(float v, __nv_bfloat16& hi, __nv_bfloat16& lo) {
    hi = __float2bfloat16(v);
    lo = __float2bfloat16(v - __bfloat162float(hi));
}

__global__ void setup_weights(const float* __restrict__ gamma_log,
                              const float* __restrict__ B_re,
                              const float* __restrict__ B_im,
                              const float* __restrict__ C_re,
                              const float* __restrict__ C_im) {
    int n = blockIdx.x;   // 0..511
    int t = threadIdx.x;  // 0..255
    int h = n & 255;
    float g = expf(gamma_log[h]);
    float w = (n < 256 ? B_re[h * DM + t] : B_im[h * DM + t]) * g;
    __nv_bfloat16 hi, lo;
    split2(w, hi, lo);
    g_W1h[n * DM + t] = hi;  g_W1l[n * DM + t] = lo;
    if (n < 256) {
        float cr = C_re[n * DH + t];
        float ci = -C_im[n * DH + t];
        split2(cr, hi, lo);
        g_W2h[n * NW1 + t] = hi;        g_W2l[n * NW1 + t] = lo;
        split2(ci, hi, lo);
        g_W2h[n * NW1 + 256 + t] = hi;  g_W2l[n * NW1 + 256 + t] = lo;
    }
}

__global__ void split_x(const float* __restrict__ x) {
    size_t i = (size_t)blockIdx.x * 256 + threadIdx.x;   // float4 index
    float4 v = ((const float4*)x)[i];
    __nv_bfloat16 h0,h1,h2,h3,l0,l1,l2,l3;
    split2(v.x,h0,l0); split2(v.y,h1,l1); split2(v.z,h2,l2); split2(v.w,h3,l3);
    size_t b = i * 4;
    *(__nv_bfloat162*)(g_xh + b)     = __nv_bfloat162(h0, h1);
    *(__nv_bfloat162*)(g_xh + b + 2) = __nv_bfloat162(h2, h3);
    *(__nv_bfloat162*)(g_xl + b)     = __nv_bfloat162(l0, l1);
    *(__nv_bfloat162*)(g_xl + b + 2) = __nv_bfloat162(l2, l3);
}

// ---------------- bf16 mma.sync GEMM (3-term split) ----------------
// C[L x NGLOB] = (Ahi+Alo)[L x KTOT] @ (Bhi+Blo)[NGLOB x KTOT]^T   (fp32 accum)
// CTA tile 128x128, K-chunk 32 (double buffered), 8 warps of 32x64.
#define KC      32
#define PITCH   80
#define TILE_B  (128 * PITCH)              // 10240
#define STAGE_B (4 * TILE_B)               // 40960
#define SMEM_BYTES (2 * STAGE_B)           // 81920
#define O_AHI 0
#define O_ALO TILE_B
#define O_BHI (2 * TILE_B)
#define O_BLO (3 * TILE_B)

template<int KTOT, int NGLOB, bool EPI>
__device__ __forceinline__ void mm_gemm_body(
    const __nv_bfloat16* __restrict__ Ahi, const __nv_bfloat16* __restrict__ Alo,
    const __nv_bfloat16* __restrict__ Bhi, const __nv_bfloat16* __restrict__ Blo,
    float* __restrict__ Cm, const float* __restrict__ X, const float* __restrict__ Dv)
{
    extern __shared__ char smem[];
    const uint32_t sb = smem_u32(smem);
    const int tid = threadIdx.x, wid = tid >> 5, l = tid & 31;
    const int rowbase = blockIdx.y * 128;
    const int colbase = blockIdx.x * 128;
    const int wm = wid & 3, wn = wid >> 2;     // warp tile: rows wm*32, cols wn*64

    float acc[2][8][4];
    #pragma unroll
    for (int i = 0; i < 2; i++)
        #pragma unroll
        for (int j = 0; j < 8; j++)
            #pragma unroll
            for (int q = 0; q < 4; q++) acc[i][j][q] = 0.f;

    const int srow = tid >> 1;
    const int sq   = (tid & 1) * 2;

    auto load_stage = [&](int c, int s) {
        const uint32_t base = sb + s * STAGE_B;
        const int k0 = c * KC;
        const __nv_bfloat16* gAh = Ahi + (size_t)(rowbase + srow) * KTOT + k0;
        const __nv_bfloat16* gAl = Alo + (size_t)(rowbase + srow) * KTOT + k0;
        const __nv_bfloat16* gBh = Bhi + (size_t)(colbase + srow) * KTOT + k0;
        const __nv_bfloat16* gBl = Blo + (size_t)(colbase + srow) * KTOT + k0;
        #pragma unroll
        for (int d = 0; d < 2; d++) {
            int q = sq + d;
            uint32_t so = srow * PITCH + q * 16;
            cp16(base + O_AHI + so, gAh + q * 8);
            cp16(base + O_ALO + so, gAl + q * 8);
            cp16(base + O_BHI + so, gBh + q * 8);
            cp16(base + O_BLO + so, gBl + q * 8);
        }
    };

    auto compute = [&](int s) {
        const uint32_t base = sb + s * STAGE_B;
        #pragma unroll
        for (int kk = 0; kk < 2; kk++) {
            const int k16 = kk * 16;
            uint32_t ah[2][4], al[2][4], bh[4][4], bl[4][4];
            #pragma unroll
            for (int mt = 0; mt < 2; mt++) {
                uint32_t ad = base + O_AHI +
                    (uint32_t)(wm * 32 + mt * 16 + (l & 15)) * PITCH +
                    (uint32_t)(k16 + ((l >> 4) << 3)) * 2;
                ldsm4(ad, ah[mt]);
            }
            const int g = l >> 3;
            const int nadd = ((g & 2) << 2) + (l & 7);
            const int kadd = k16 + ((g & 1) << 3);
            #pragma unroll
            for (int p = 0; p < 4; p++) {
                uint32_t bd = base + O_BHI +
                    (uint32_t)(wn * 64 + p * 16 + nadd) * PITCH + (uint32_t)kadd * 2;
                ldsm4(bd, bh[p]);
            }
            #pragma unroll
            for (int mt = 0; mt < 2; mt++)
                #pragma unroll
                for (int nt = 0; nt < 8; nt++)
                    mma_bf16(acc[mt][nt], ah[mt], &bh[nt >> 1][(nt & 1) * 2]);
            #pragma unroll
            for (int mt = 0; mt < 2; mt++) {
                uint32_t ad = base + O_ALO +
                    (uint32_t)(wm * 32 + mt * 16 + (l & 15)) * PITCH +
                    (uint32_t)(k16 + ((l >> 4) << 3)) * 2;
                ldsm4(ad, al[mt]);
            }
            #pragma unroll
            for (int mt = 0; mt < 2; mt++)
                #pragma unroll
                for (int nt = 0; nt < 8; nt++)
                    mma_bf16(acc[mt][nt], al[mt], &bh[nt >> 1][(nt & 1) * 2]);
            #pragma unroll
            for (int p = 0; p < 4; p++) {
                uint32_t bd = base + O_BLO +
                    (uint32_t)(wn * 64 + p * 16 + nadd) * PITCH + (uint32_t)kadd * 2;
                ldsm4(bd, bl[p]);
            }
            #pragma unroll
            for (int mt = 0; mt < 2; mt++)
                #pragma unroll
                for (int nt = 0; nt < 8; nt++)
                    mma_bf16(acc[mt][nt], ah[mt], &bl[nt >> 1][(nt & 1) * 2]);
        }
    };

    const int NCH = KTOT / KC;
    load_stage(0, 0);
    cp_commit();
    for (int c = 0; c < NCH; c++) {
        if (c + 1 < NCH) {
            load_stage(c + 1, (c + 1) & 1);
            cp_commit();
            asm volatile("cp.async.wait_group 1;" ::: "memory");
        } else {
            asm volatile("cp.async.wait_group 0;" ::: "memory");
        }
        __syncthreads();
        compute(c & 1);
        __syncthreads();
    }

    const int erow = (l >> 2);
    const int ecol = (l & 3) * 2;
    #pragma unroll
    for (int mt = 0; mt < 2; mt++) {
        #pragma unroll
        for (int nt = 0; nt < 8; nt++) {
            int r0 = rowbase + wm * 32 + mt * 16 + erow;
            int c0 = colbase + wn * 64 + nt * 8 + ecol;
            float2 v0 = make_float2(acc[mt][nt][0], acc[mt][nt][1]);
            float2 v1 = make_float2(acc[mt][nt][2], acc[mt][nt][3]);
            if (EPI) {
                float2 x0 = *(const float2*)&X[(size_t)r0 * DM + c0];
                float2 x1 = *(const float2*)&X[(size_t)(r0 + 8) * DM + c0];
                float2 dv = *(const float2*)&Dv[c0];
                v0.x = fmaf(x0.x, dv.x, v0.x); v0.y = fmaf(x0.y, dv.y, v0.y);
                v1.x = fmaf(x1.x, dv.x, v1.x); v1.y = fmaf(x1.y, dv.y, v1.y);
            }
            *(float2*)&Cm[(size_t)r0 * NGLOB + c0]       = v0;
            *(float2*)&Cm[(size_t)(r0 + 8) * NGLOB + c0] = v1;
        }
    }
}

// Wrappers: bind __device__ globals from DEVICE code (host-side symbol
// references would silently resolve to the host shadow via ATS -> zeros).
__global__ void __launch_bounds__(256, 2) gemm1_k() {
    mm_gemm_body<DM, NW1, false>(g_xh, g_xl, g_W1h, g_W1l, g_Bu, nullptr, nullptr);
}
__global__ void __launch_bounds__(256, 2) gemm2_k(float* __restrict__ y,
                                                  const float* __restrict__ X,
                                                  const float* __restrict__ Dv) {
    mm_gemm_body<NW1, DM, true>(g_hh, g_hl, g_W2h, g_W2l, y, X, Dv);
}

// ---------------- chunked scan ----------------
__global__ void scan_carry() {
    int c = blockIdx.x, ch = threadIdx.x;
    float2 lam = g_lam[ch];
    float hr = 0.f, hi = 0.f;
    const float* base = g_Bu + (size_t)c * CHUNK * NW1;
    #pragma unroll 4
    for (int t = 0; t < CHUNK; t++) {
        float br = base[t * NW1 + ch];
        float bi = base[t * NW1 + DH + ch];
        float nr = fmaf(lam.x, hr, br);  nr = fmaf(-lam.y, hi, nr);
        float ni = fmaf(lam.x, hi, bi);  ni = fmaf( lam.y, hr, ni);
        hr = nr; hi = ni;
    }
    g_carry[c * DH + ch] = make_float2(hr, hi);
}

__global__ void chunk_prefix() {
    int ch = threadIdx.x;
    float2 lamT = g_lamT[ch];
    float hr = 0.f, hi = 0.f;
    for (int c = 0; c < NCHUNK; c++) {
        g_hinit[c * DH + ch] = make_float2(hr, hi);
        float2 b = g_carry[c * DH + ch];
        float nr = fmaf(lamT.x, hr, b.x);  nr = fmaf(-lamT.y, hi, nr);
        float ni = fmaf(lamT.x, hi, b.y);  ni = fmaf( lamT.y, hr, ni);
        hr = nr; hi = ni;
    }
}

__global__ void scan_apply() {
    int c = blockIdx.x, ch = threadIdx.x;
    float2 lam = g_lam[ch];
    float2 h0  = g_hinit[c * DH + ch];
    float hr = h0.x, hi = h0.y;
    const float* base = g_Bu + (size_t)c * CHUNK * NW1;
    __nv_bfloat16* oh = g_hh + (size_t)c * CHUNK * NW1;
    __nv_bfloat16* ol = g_hl + (size_t)c * CHUNK * NW1;
    #pragma unroll 2
    for (int t = 0; t < CHUNK; t++) {
        float br = base[t * NW1 + ch];
        float bi = base[t * NW1 + DH + ch];
        float nr = fmaf(lam.x, hr, br);  nr = fmaf(-lam.y, hi, nr);
        float ni = fmaf(lam.x, hi, bi);  ni = fmaf( lam.y, hr, ni);
        hr = nr; hi = ni;
        __nv_bfloat16 a, b2;
        split2(hr, a, b2);
        oh[t * NW1 + ch] = a;       ol[t * NW1 + ch] = b2;
        split2(hi, a, b2);
        oh[t * NW1 + DH + ch] = a;  ol[t * NW1 + DH + ch] = b2;
    }
}

// ---------------- entry ----------------
extern "C" void kernel_launch(void* const* d_in, const int* in_sizes, int n_in,
                              void* d_out, int out_size) {
    const float* x         = (const float*)d_in[0];
    const float* nu_log    = (const float*)d_in[1];
    const float* theta_log = (const float*)d_in[2];
    const float* gamma_log = (const float*)d_in[3];
    const float* B_re      = (const float*)d_in[4];
    const float* B_im      = (const float*)d_in[5];
    const float* C_re      = (const float*)d_in[6];
    const float* C_im      = (const float*)d_in[7];
    const float* Dv        = (const float*)d_in[8];
    float* y = (float*)d_out;

    cudaFuncSetAttribute(gemm1_k, cudaFuncAttributeMaxDynamicSharedMemorySize, SMEM_BYTES);
    cudaFuncSetAttribute(gemm2_k, cudaFuncAttributeMaxDynamicSharedMemorySize, SMEM_BYTES);

    setup_params<<<1, 256>>>(nu_log, theta_log);
    setup_weights<<<512, 256>>>(gamma_log, B_re, B_im, C_re, C_im);
    split_x<<<(L_SEQ * DM / 4) / 256, 256>>>(x);

    // GEMM1: Bu[L x 512] = x @ W1T^T
    gemm1_k<<<dim3(NW1 / 128, L_SEQ / 128), 256, SMEM_BYTES>>>();

    scan_carry<<<NCHUNK, DH>>>();
    chunk_prefix<<<1, DH>>>();
    scan_apply<<<NCHUNK, DH>>>();

    // GEMM2: y[L x 256] = h @ W2T^T + x*D
    gemm2_k<<<dim3(DM / 128, L_SEQ / 128), 256, SMEM_BYTES>>>(y, x, Dv);
}

// round 5
// speedup vs baseline: 2.0177x; 1.1745x over previous
#include <cuda_runtime.h>
#include <cuda_bf16.h>
#include <cmath>
#include <cstdint>

#define L_SEQ  32768
#define DM     256
#define DH     256
#define NW1    512
#define CHUNK  64
#define NCHUNK (L_SEQ / CHUNK)   // 512

// ---------------- scratch ----------------
// Channel-interleaved layout: col 2h = re_h, col 2h+1 = im_h.
__device__ float          g_Bu[(size_t)L_SEQ * NW1];          // GEMM1 out (fp32), scan input
__device__ __nv_bfloat16  g_xh[(size_t)L_SEQ * DM];
__device__ __nv_bfloat16  g_xl[(size_t)L_SEQ * DM];
__device__ __nv_bfloat16  g_hh[(size_t)L_SEQ * NW1];
__device__ __nv_bfloat16  g_hl[(size_t)L_SEQ * NW1];
__device__ __nv_bfloat16  g_W1h[NW1 * DM], g_W1l[NW1 * DM];   // [512][256]
__device__ __nv_bfloat16  g_W2h[DM * NW1], g_W2l[DM * NW1];   // [256][512]
__device__ float2         g_lam[DH];
__device__ float2         g_lamPow[9 * DH];                   // lamT^(2^s)
__device__ float          g_carryf[NCHUNK * NW1];
__device__ float          g_hinitf[NCHUNK * NW1];

// ---------------- PTX helpers ----------------
__device__ __forceinline__ uint32_t smem_u32(const void* p) {
    uint32_t a;
    asm("{ .reg .u64 t; cvta.to.shared.u64 t, %1; cvt.u32.u64 %0, t; }" : "=r"(a) : "l"(p));
    return a;
}
__device__ __forceinline__ void cp16(uint32_t s, const void* g) {
    asm volatile("cp.async.cg.shared.global [%0], [%1], 16;" :: "r"(s), "l"(g));
}
__device__ __forceinline__ void cp_commit() {
    asm volatile("cp.async.commit_group;" ::: "memory");
}
__device__ __forceinline__ void ldsm4(uint32_t addr, uint32_t* r) {
    asm volatile("ldmatrix.sync.aligned.m8n8.x4.shared.b16 {%0,%1,%2,%3}, [%4];"
                 : "=r"(r[0]), "=r"(r[1]), "=r"(r[2]), "=r"(r[3]) : "r"(addr));
}
__device__ __forceinline__ void mma_bf16(float* c, const uint32_t* a, const uint32_t* b) {
    asm volatile("mma.sync.aligned.m16n8k16.row.col.f32.bf16.bf16.f32 "
                 "{%0,%1,%2,%3},{%4,%5,%6,%7},{%8,%9},{%0,%1,%2,%3};"
                 : "+f"(c[0]), "+f"(c[1]), "+f"(c[2]), "+f"(c[3])
                 : "r"(a[0]), "r"(a[1]), "r"(a[2]), "r"(a[3]), "r"(b[0]), "r"(b[1]));
}

// ---------------- setup ----------------
__global__ void setup_params(const float* __restrict__ nu_log,
                             const float* __restrict__ theta_log) {
    int h = threadIdx.x;
    double nu = exp((double)nu_log[h]);
    double th = exp((double)theta_log[h]);
    double r  = exp(-nu);
    g_lam[h]  = make_float2((float)(r * cos(th)), (float)(r * sin(th)));
    #pragma unroll
    for (int s = 0; s < 9; s++) {
        double sc = (double)CHUNK * (double)(1 << s);
        double rr = exp(-sc * nu);
        double aa = sc * th;
        g_lamPow[s * DH + h] = make_float2((float)(rr * cos(aa)), (float)(rr * sin(aa)));
    }
}

__device__ __forceinline__ void split2(float v, __nv_bfloat16& hi, __nv_bfloat16& lo) {
    hi = __float2bfloat16(v);
    lo = __float2bfloat16(v - __bfloat162float(hi));
}

__global__ void setup_weights(const float* __restrict__ gamma_log,
                              const float* __restrict__ B_re,
                              const float* __restrict__ B_im,
                              const float* __restrict__ C_re,
                              const float* __restrict__ C_im) {
    int n = blockIdx.x;   // 0..511 : channel-interleaved index (2h=re, 2h+1=im)
    int t = threadIdx.x;  // 0..255
    int h = n >> 1;
    int im = n & 1;
    float g = expf(gamma_log[h]);
    float w = (im ? B_im[h * DM + t] : B_re[h * DM + t]) * g;
    __nv_bfloat16 hi, lo;
    split2(w, hi, lo);
    g_W1h[n * DM + t] = hi;  g_W1l[n * DM + t] = lo;
    // W2T row (m=t), col k=n: k=2h -> C_re[t][h], k=2h+1 -> -C_im[t][h]
    float c2 = im ? -C_im[t * DH + h] : C_re[t * DH + h];
    split2(c2, hi, lo);
    g_W2h[t * NW1 + n] = hi;  g_W2l[t * NW1 + n] = lo;
}

__global__ void split_x(const float* __restrict__ x) {
    size_t i = (size_t)blockIdx.x * 256 + threadIdx.x;   // float4 index
    float4 v = ((const float4*)x)[i];
    __nv_bfloat16 h0,h1,h2,h3,l0,l1,l2,l3;
    split2(v.x,h0,l0); split2(v.y,h1,l1); split2(v.z,h2,l2); split2(v.w,h3,l3);
    size_t b = i * 4;
    *(__nv_bfloat162*)(g_xh + b)     = __nv_bfloat162(h0, h1);
    *(__nv_bfloat162*)(g_xh + b + 2) = __nv_bfloat162(h2, h3);
    *(__nv_bfloat162*)(g_xl + b)     = __nv_bfloat162(l0, l1);
    *(__nv_bfloat162*)(g_xl + b + 2) = __nv_bfloat162(l2, l3);
}

// ---------------- bf16 mma.sync GEMM (3-term split, 4-stage pipeline) --------
#define KC      32
#define PITCH   80
#define TILE_B  (128 * PITCH)              // 10240
#define STAGE_B (4 * TILE_B)               // 40960
#define NSTAGE  4
#define SMEM_BYTES (NSTAGE * STAGE_B)      // 163840
#define O_AHI 0
#define O_ALO TILE_B
#define O_BHI (2 * TILE_B)
#define O_BLO (3 * TILE_B)

template<int KTOT, int NGLOB, bool EPI>
__device__ __forceinline__ void mm_gemm_body(
    const __nv_bfloat16* __restrict__ Ahi, const __nv_bfloat16* __restrict__ Alo,
    const __nv_bfloat16* __restrict__ Bhi, const __nv_bfloat16* __restrict__ Blo,
    float* __restrict__ Cm, const float* __restrict__ X, const float* __restrict__ Dv)
{
    extern __shared__ char smem[];
    const uint32_t sb = smem_u32(smem);
    const int tid = threadIdx.x, wid = tid >> 5, l = tid & 31;
    const int rowbase = blockIdx.y * 128;
    const int colbase = blockIdx.x * 128;
    const int wm = wid & 3, wn = wid >> 2;

    float acc[2][8][4];
    #pragma unroll
    for (int i = 0; i < 2; i++)
        #pragma unroll
        for (int j = 0; j < 8; j++)
            #pragma unroll
            for (int q = 0; q < 4; q++) acc[i][j][q] = 0.f;

    const int srow = tid >> 1;
    const int sq   = (tid & 1) * 2;

    auto load_stage = [&](int c) {
        const uint32_t base = sb + (c & (NSTAGE - 1)) * STAGE_B;
        const int k0 = c * KC;
        const __nv_bfloat16* gAh = Ahi + (size_t)(rowbase + srow) * KTOT + k0;
        const __nv_bfloat16* gAl = Alo + (size_t)(rowbase + srow) * KTOT + k0;
        const __nv_bfloat16* gBh = Bhi + (size_t)(colbase + srow) * KTOT + k0;
        const __nv_bfloat16* gBl = Blo + (size_t)(colbase + srow) * KTOT + k0;
        #pragma unroll
        for (int d = 0; d < 2; d++) {
            int q = sq + d;
            uint32_t so = srow * PITCH + q * 16;
            cp16(base + O_AHI + so, gAh + q * 8);
            cp16(base + O_ALO + so, gAl + q * 8);
            cp16(base + O_BHI + so, gBh + q * 8);
            cp16(base + O_BLO + so, gBl + q * 8);
        }
    };

    auto compute = [&](int c) {
        const uint32_t base = sb + (c & (NSTAGE - 1)) * STAGE_B;
        #pragma unroll
        for (int kk = 0; kk < 2; kk++) {
            const int k16 = kk * 16;
            uint32_t ah[2][4], al[2][4], bh[4][4], bl[4][4];
            const uint32_t arow_off =
                (uint32_t)(wm * 32 + (l & 15)) * PITCH + (uint32_t)(k16 + ((l >> 4) << 3)) * 2;
            const int g = l >> 3;
            const int nadd = ((g & 2) << 2) + (l & 7);
            const int kadd = k16 + ((g & 1) << 3);
            // issue all hi ldsm + lo-A ldsm up front so latency hides behind MMAs
            #pragma unroll
            for (int mt = 0; mt < 2; mt++)
                ldsm4(base + O_AHI + arow_off + (uint32_t)(mt * 16) * PITCH, ah[mt]);
            #pragma unroll
            for (int p = 0; p < 4; p++)
                ldsm4(base + O_BHI + (uint32_t)(wn * 64 + p * 16 + nadd) * PITCH
                           + (uint32_t)kadd * 2, bh[p]);
            #pragma unroll
            for (int mt = 0; mt < 2; mt++)
                ldsm4(base + O_ALO + arow_off + (uint32_t)(mt * 16) * PITCH, al[mt]);
            // term 1: ah * bh
            #pragma unroll
            for (int mt = 0; mt < 2; mt++)
                #pragma unroll
                for (int nt = 0; nt < 8; nt++)
                    mma_bf16(acc[mt][nt], ah[mt], &bh[nt >> 1][(nt & 1) * 2]);
            // prefetch lo-B while term-2 runs
            #pragma unroll
            for (int p = 0; p < 4; p++)
                ldsm4(base + O_BLO + (uint32_t)(wn * 64 + p * 16 + nadd) * PITCH
                           + (uint32_t)kadd * 2, bl[p]);
            // term 2: al * bh
            #pragma unroll
            for (int mt = 0; mt < 2; mt++)
                #pragma unroll
                for (int nt = 0; nt < 8; nt++)
                    mma_bf16(acc[mt][nt], al[mt], &bh[nt >> 1][(nt & 1) * 2]);
            // term 3: ah * bl
            #pragma unroll
            for (int mt = 0; mt < 2; mt++)
                #pragma unroll
                for (int nt = 0; nt < 8; nt++)
                    mma_bf16(acc[mt][nt], ah[mt], &bl[nt >> 1][(nt & 1) * 2]);
        }
    };

    const int NCH = KTOT / KC;
    load_stage(0); cp_commit();
    load_stage(1); cp_commit();
    load_stage(2); cp_commit();
    for (int c = 0; c < NCH; c++) {
        asm volatile("cp.async.wait_group 2;" ::: "memory");
        __syncthreads();
        compute(c);
        __syncthreads();
        if (c + 3 < NCH) load_stage(c + 3);
        cp_commit();   // empty groups at tail keep wait_group(2) semantics uniform
    }

    const int erow = (l >> 2);
    const int ecol = (l & 3) * 2;
    #pragma unroll
    for (int mt = 0; mt < 2; mt++) {
        #pragma unroll
        for (int nt = 0; nt < 8; nt++) {
            int r0 = rowbase + wm * 32 + mt * 16 + erow;
            int c0 = colbase + wn * 64 + nt * 8 + ecol;
            float2 v0 = make_float2(acc[mt][nt][0], acc[mt][nt][1]);
            float2 v1 = make_float2(acc[mt][nt][2], acc[mt][nt][3]);
            if (EPI) {
                float2 x0 = *(const float2*)&X[(size_t)r0 * DM + c0];
                float2 x1 = *(const float2*)&X[(size_t)(r0 + 8) * DM + c0];
                float2 dv = *(const float2*)&Dv[c0];
                v0.x = fmaf(x0.x, dv.x, v0.x); v0.y = fmaf(x0.y, dv.y, v0.y);
                v1.x = fmaf(x1.x, dv.x, v1.x); v1.y = fmaf(x1.y, dv.y, v1.y);
            }
            *(float2*)&Cm[(size_t)r0 * NGLOB + c0]       = v0;
            *(float2*)&Cm[(size_t)(r0 + 8) * NGLOB + c0] = v1;
        }
    }
}

// Wrappers: bind __device__ globals from DEVICE code only.
__global__ void __launch_bounds__(256, 1) gemm1_k() {
    mm_gemm_body<DM, NW1, false>(g_xh, g_xl, g_W1h, g_W1l, g_Bu, nullptr, nullptr);
}
__global__ void __launch_bounds__(256, 1) gemm2_k(float* __restrict__ y,
                                                  const float* __restrict__ X,
                                                  const float* __restrict__ Dv) {
    mm_gemm_body<NW1, DM, true>(g_hh, g_hl, g_W2h, g_W2l, y, X, Dv);
}

// ---------------- chunked scan (interleaved: float4 = 2 complex channels) ----
__global__ void scan_carry() {
    int c = blockIdx.x, j = threadIdx.x;   // j: 0..127
    float2 l0 = g_lam[2 * j], l1 = g_lam[2 * j + 1];
    float4 h = make_float4(0.f, 0.f, 0.f, 0.f);
    const float4* base = (const float4*)(g_Bu + (size_t)c * CHUNK * NW1) + j;
    #pragma unroll 8
    for (int t = 0; t < CHUNK; t++) {
        float4 v = base[(size_t)t * 128];
        float nr0 = fmaf(l0.x, h.x, fmaf(-l0.y, h.y, v.x));
        float ni0 = fmaf(l0.x, h.y, fmaf( l0.y, h.x, v.y));
        float nr1 = fmaf(l1.x, h.z, fmaf(-l1.y, h.w, v.z));
        float ni1 = fmaf(l1.x, h.w, fmaf( l1.y, h.z, v.w));
        h = make_float4(nr0, ni0, nr1, ni1);
    }
    ((float4*)g_carryf)[c * 128 + j] = h;
}

// Kogge-Stone exclusive prefix over chunks: hinit[c] = sum_{i<c} lamT^(c-1-i) carry[i]
__global__ void chunk_prefix_ks() {
    __shared__ float4 sm[NCHUNK];
    int c = threadIdx.x, j = blockIdx.x;   // j: channel pair 0..127
    float4 x = ((const float4*)g_carryf)[c * 128 + j];
    sm[c] = x;
    __syncthreads();
    #pragma unroll
    for (int s = 0; s < 9; s++) {
        int d = 1 << s;
        float4 pv = make_float4(0.f, 0.f, 0.f, 0.f);
        if (c >= d) pv = sm[c - d];
        float2 p0 = g_lamPow[s * DH + 2 * j];
        float2 p1 = g_lamPow[s * DH + 2 * j + 1];
        __syncthreads();
        if (c >= d) {
            x.x += p0.x * pv.x - p0.y * pv.y;
            x.y += p0.x * pv.y + p0.y * pv.x;
            x.z += p1.x * pv.z - p1.y * pv.w;
            x.w += p1.x * pv.w + p1.y * pv.z;
        }
        sm[c] = x;
        __syncthreads();
    }
    float4 out = make_float4(0.f, 0.f, 0.f, 0.f);
    if (c > 0) out = sm[c - 1];
    ((float4*)g_hinitf)[c * 128 + j] = out;
}

__global__ void scan_apply() {
    int c = blockIdx.x, j = threadIdx.x;
    float2 l0 = g_lam[2 * j], l1 = g_lam[2 * j + 1];
    float4 h = ((const float4*)g_hinitf)[c * 128 + j];
    const float4* base = (const float4*)(g_Bu + (size_t)c * CHUNK * NW1) + j;
    __nv_bfloat16* oh = g_hh + (size_t)c * CHUNK * NW1 + 4 * j;
    __nv_bfloat16* ol = g_hl + (size_t)c * CHUNK * NW1 + 4 * j;
    #pragma unroll 4
    for (int t = 0; t < CHUNK; t++) {
        float4 v = base[(size_t)t * 128];
        float nr0 = fmaf(l0.x, h.x, fmaf(-l0.y, h.y, v.x));
        float ni0 = fmaf(l0.x, h.y, fmaf( l0.y, h.x, v.y));
        float nr1 = fmaf(l1.x, h.z, fmaf(-l1.y, h.w, v.z));
        float ni1 = fmaf(l1.x, h.w, fmaf( l1.y, h.z, v.w));
        h = make_float4(nr0, ni0, nr1, ni1);
        __nv_bfloat16 a0,b0,a1,b1,a2,b2,a3,b3;
        split2(nr0, a0, b0); split2(ni0, a1, b1);
        split2(nr1, a2, b2); split2(ni1, a3, b3);
        __nv_bfloat162 ph0(a0, a1), ph1(a2, a3), pl0(b0, b1), pl1(b2, b3);
        uint2 uh, ul;
        uh.x = *reinterpret_cast<uint32_t*>(&ph0); uh.y = *reinterpret_cast<uint32_t*>(&ph1);
        ul.x = *reinterpret_cast<uint32_t*>(&pl0); ul.y = *reinterpret_cast<uint32_t*>(&pl1);
        *reinterpret_cast<uint2*>(oh + (size_t)t * NW1) = uh;
        *reinterpret_cast<uint2*>(ol + (size_t)t * NW1) = ul;
    }
}

// ---------------- entry ----------------
extern "C" void kernel_launch(void* const* d_in, const int* in_sizes, int n_in,
                              void* d_out, int out_size) {
    const float* x         = (const float*)d_in[0];
    const float* nu_log    = (const float*)d_in[1];
    const float* theta_log = (const float*)d_in[2];
    const float* gamma_log = (const float*)d_in[3];
    const float* B_re      = (const float*)d_in[4];
    const float* B_im      = (const float*)d_in[5];
    const float* C_re      = (const float*)d_in[6];
    const float* C_im      = (const float*)d_in[7];
    const float* Dv        = (const float*)d_in[8];
    float* y = (float*)d_out;

    cudaFuncSetAttribute(gemm1_k, cudaFuncAttributeMaxDynamicSharedMemorySize, SMEM_BYTES);
    cudaFuncSetAttribute(gemm2_k, cudaFuncAttributeMaxDynamicSharedMemorySize, SMEM_BYTES);

    setup_params<<<1, 256>>>(nu_log, theta_log);
    setup_weights<<<512, 256>>>(gamma_log, B_re, B_im, C_re, C_im);
    split_x<<<(L_SEQ * DM / 4) / 256, 256>>>(x);

    // GEMM1: Bu[L x 512] = x @ W1T^T
    gemm1_k<<<dim3(NW1 / 128, L_SEQ / 128), 256, SMEM_BYTES>>>();

    scan_carry<<<NCHUNK, 128>>>();
    chunk_prefix_ks<<<128, NCHUNK>>>();
    scan_apply<<<NCHUNK, 128>>>();

    // GEMM2: y[L x 256] = h @ W2T^T + x*D
    gemm2_k<<<dim3(DM / 128, L_SEQ / 128), 256, SMEM_BYTES>>>(y, x, Dv);
}

// round 6
// speedup vs baseline: 2.3384x; 1.1589x over previous
#include <cuda_runtime.h>
#include <cuda_bf16.h>
#include <cmath>
#include <cstdint>

#define L_SEQ  32768
#define DM     256
#define DH     256
#define NW1    512
#define CHUNK  64
#define NCHUNK (L_SEQ / CHUNK)   // 512

// ---------------- scratch ----------------
// Channel-interleaved layout: col 2h = re_h, col 2h+1 = im_h.
__device__ float          g_Bu[(size_t)L_SEQ * NW1];
__device__ __nv_bfloat16  g_xh[(size_t)L_SEQ * DM];
__device__ __nv_bfloat16  g_xl[(size_t)L_SEQ * DM];
__device__ __nv_bfloat16  g_hh[(size_t)L_SEQ * NW1];
__device__ __nv_bfloat16  g_hl[(size_t)L_SEQ * NW1];
__device__ __nv_bfloat16  g_W1h[NW1 * DM];                    // [512][256] (hi only: 2-term)
__device__ __nv_bfloat16  g_W2h[DM * NW1], g_W2l[DM * NW1];   // [256][512]
__device__ float2         g_lam[DH];
__device__ float2         g_lamPow[9 * DH];
__device__ float          g_carryf[NCHUNK * NW1];
__device__ float          g_hinitf[NCHUNK * NW1];

// ---------------- PTX helpers ----------------
__device__ __forceinline__ uint32_t smem_u32(const void* p) {
    uint32_t a;
    asm("{ .reg .u64 t; cvta.to.shared.u64 t, %1; cvt.u32.u64 %0, t; }" : "=r"(a) : "l"(p));
    return a;
}
__device__ __forceinline__ void cp16(uint32_t s, const void* g) {
    asm volatile("cp.async.cg.shared.global [%0], [%1], 16;" :: "r"(s), "l"(g));
}
__device__ __forceinline__ void cp_commit() {
    asm volatile("cp.async.commit_group;" ::: "memory");
}
__device__ __forceinline__ void ldsm4(uint32_t addr, uint32_t* r) {
    asm volatile("ldmatrix.sync.aligned.m8n8.x4.shared.b16 {%0,%1,%2,%3}, [%4];"
                 : "=r"(r[0]), "=r"(r[1]), "=r"(r[2]), "=r"(r[3]) : "r"(addr));
}
__device__ __forceinline__ void mma_bf16(float* c, const uint32_t* a, const uint32_t* b) {
    asm volatile("mma.sync.aligned.m16n8k16.row.col.f32.bf16.bf16.f32 "
                 "{%0,%1,%2,%3},{%4,%5,%6,%7},{%8,%9},{%0,%1,%2,%3};"
                 : "+f"(c[0]), "+f"(c[1]), "+f"(c[2]), "+f"(c[3])
                 : "r"(a[0]), "r"(a[1]), "r"(a[2]), "r"(a[3]), "r"(b[0]), "r"(b[1]));
}

// ---------------- setup ----------------
__global__ void setup_params(const float* __restrict__ nu_log,
                             const float* __restrict__ theta_log) {
    int h = threadIdx.x;
    double nu = exp((double)nu_log[h]);
    double th = exp((double)theta_log[h]);
    double r  = exp(-nu);
    g_lam[h]  = make_float2((float)(r * cos(th)), (float)(r * sin(th)));
    #pragma unroll
    for (int s = 0; s < 9; s++) {
        double sc = (double)CHUNK * (double)(1 << s);
        double rr = exp(-sc * nu);
        double aa = sc * th;
        g_lamPow[s * DH + h] = make_float2((float)(rr * cos(aa)), (float)(rr * sin(aa)));
    }
}

__device__ __forceinline__ void split2(float v, __nv_bfloat16& hi, __nv_bfloat16& lo) {
    hi = __float2bfloat16(v);
    lo = __float2bfloat16(v - __bfloat162float(hi));
}

__global__ void setup_weights(const float* __restrict__ gamma_log,
                              const float* __restrict__ B_re,
                              const float* __restrict__ B_im,
                              const float* __restrict__ C_re,
                              const float* __restrict__ C_im) {
    int n = blockIdx.x;   // 0..511 : channel-interleaved (2h=re, 2h+1=im)
    int t = threadIdx.x;  // 0..255
    int h = n >> 1;
    int im = n & 1;
    float g = expf(gamma_log[h]);
    float w = (im ? B_im[h * DM + t] : B_re[h * DM + t]) * g;
    g_W1h[n * DM + t] = __float2bfloat16(w);     // hi only (2-term GEMM1)
    float c2 = im ? -C_im[t * DH + h] : C_re[t * DH + h];
    __nv_bfloat16 hi, lo;
    split2(c2, hi, lo);
    g_W2h[t * NW1 + n] = hi;  g_W2l[t * NW1 + n] = lo;
}

__global__ void split_x(const float* __restrict__ x) {
    size_t i = (size_t)blockIdx.x * 256 + threadIdx.x;
    float4 v = ((const float4*)x)[i];
    __nv_bfloat16 h0,h1,h2,h3,l0,l1,l2,l3;
    split2(v.x,h0,l0); split2(v.y,h1,l1); split2(v.z,h2,l2); split2(v.w,h3,l3);
    size_t b = i * 4;
    *(__nv_bfloat162*)(g_xh + b)     = __nv_bfloat162(h0, h1);
    *(__nv_bfloat162*)(g_xh + b + 2) = __nv_bfloat162(h2, h3);
    *(__nv_bfloat162*)(g_xl + b)     = __nv_bfloat162(l0, l1);
    *(__nv_bfloat162*)(g_xl + b + 2) = __nv_bfloat162(l2, l3);
}

// ---------------- bf16 mma.sync GEMM (split terms, multi-stage pipeline) -----
#define KC      32
#define PITCH   80
#define TILE_B  (128 * PITCH)              // 10240
#define O_AHI 0
#define O_ALO TILE_B
#define O_BHI (2 * TILE_B)
#define O_BLO (3 * TILE_B)
#define SMEM1 (3 * 3 * TILE_B)             // gemm1: 3 tiles x 3 stages = 92160
#define SMEM2 (2 * 4 * TILE_B)             // gemm2: 4 tiles x 2 stages = 81920

template<int KTOT, int NGLOB, int NSTAGE, int NTERMS, bool EPI>
__device__ __forceinline__ void mm_gemm_body(
    const __nv_bfloat16* __restrict__ Ahi, const __nv_bfloat16* __restrict__ Alo,
    const __nv_bfloat16* __restrict__ Bhi, const __nv_bfloat16* __restrict__ Blo,
    float* __restrict__ Cm, const float* __restrict__ X, const float* __restrict__ Dv)
{
    constexpr int NTILE  = (NTERMS == 3) ? 4 : 3;
    constexpr int STAGEB = NTILE * TILE_B;
    extern __shared__ char smem[];
    const uint32_t sb = smem_u32(smem);
    const int tid = threadIdx.x, wid = tid >> 5, l = tid & 31;
    const int rowbase = blockIdx.y * 128;
    const int colbase = blockIdx.x * 128;
    const int wm = wid & 3, wn = wid >> 2;

    float acc[2][8][4];
    #pragma unroll
    for (int i = 0; i < 2; i++)
        #pragma unroll
        for (int j = 0; j < 8; j++)
            #pragma unroll
            for (int q = 0; q < 4; q++) acc[i][j][q] = 0.f;

    const int srow = tid >> 1;
    const int sq   = (tid & 1) * 2;

    auto load_stage = [&](int c) {
        const uint32_t base = sb + (c % NSTAGE) * STAGEB;
        const int k0 = c * KC;
        const __nv_bfloat16* gAh = Ahi + (size_t)(rowbase + srow) * KTOT + k0;
        const __nv_bfloat16* gAl = Alo + (size_t)(rowbase + srow) * KTOT + k0;
        const __nv_bfloat16* gBh = Bhi + (size_t)(colbase + srow) * KTOT + k0;
        #pragma unroll
        for (int d = 0; d < 2; d++) {
            int q = sq + d;
            uint32_t so = srow * PITCH + q * 16;
            cp16(base + O_AHI + so, gAh + q * 8);
            cp16(base + O_ALO + so, gAl + q * 8);
            cp16(base + O_BHI + so, gBh + q * 8);
            if (NTERMS == 3) {
                const __nv_bfloat16* gBl = Blo + (size_t)(colbase + srow) * KTOT + k0;
                cp16(base + O_BLO + so, gBl + q * 8);
            }
        }
    };

    auto compute = [&](int c) {
        const uint32_t base = sb + (c % NSTAGE) * STAGEB;
        #pragma unroll
        for (int kk = 0; kk < 2; kk++) {
            const int k16 = kk * 16;
            uint32_t ah[2][4], al[2][4], bh[4][4], bl[4][4];
            const uint32_t arow_off =
                (uint32_t)(wm * 32 + (l & 15)) * PITCH + (uint32_t)(k16 + ((l >> 4) << 3)) * 2;
            const int g = l >> 3;
            const int nadd = ((g & 2) << 2) + (l & 7);
            const int kadd = k16 + ((g & 1) << 3);
            #pragma unroll
            for (int mt = 0; mt < 2; mt++)
                ldsm4(base + O_AHI + arow_off + (uint32_t)(mt * 16) * PITCH, ah[mt]);
            #pragma unroll
            for (int p = 0; p < 4; p++)
                ldsm4(base + O_BHI + (uint32_t)(wn * 64 + p * 16 + nadd) * PITCH
                           + (uint32_t)kadd * 2, bh[p]);
            #pragma unroll
            for (int mt = 0; mt < 2; mt++)
                ldsm4(base + O_ALO + arow_off + (uint32_t)(mt * 16) * PITCH, al[mt]);
            // term 1: ah * bh
            #pragma unroll
            for (int mt = 0; mt < 2; mt++)
                #pragma unroll
                for (int nt = 0; nt < 8; nt++)
                    mma_bf16(acc[mt][nt], ah[mt], &bh[nt >> 1][(nt & 1) * 2]);
            if (NTERMS == 3) {
                #pragma unroll
                for (int p = 0; p < 4; p++)
                    ldsm4(base + O_BLO + (uint32_t)(wn * 64 + p * 16 + nadd) * PITCH
                               + (uint32_t)kadd * 2, bl[p]);
            }
            // term 2: al * bh
            #pragma unroll
            for (int mt = 0; mt < 2; mt++)
                #pragma unroll
                for (int nt = 0; nt < 8; nt++)
                    mma_bf16(acc[mt][nt], al[mt], &bh[nt >> 1][(nt & 1) * 2]);
            // term 3: ah * bl
            if (NTERMS == 3) {
                #pragma unroll
                for (int mt = 0; mt < 2; mt++)
                    #pragma unroll
                    for (int nt = 0; nt < 8; nt++)
                        mma_bf16(acc[mt][nt], ah[mt], &bl[nt >> 1][(nt & 1) * 2]);
            }
        }
    };

    const int NCH = KTOT / KC;
    #pragma unroll
    for (int s = 0; s < NSTAGE - 1; s++) { load_stage(s); cp_commit(); }
    for (int c = 0; c < NCH; c++) {
        if (c + NSTAGE - 1 < NCH) load_stage(c + NSTAGE - 1);
        cp_commit();                       // (possibly empty) group keeps counts uniform
        asm volatile("cp.async.wait_group %0;" :: "n"(NSTAGE - 1) : "memory");
        __syncthreads();
        compute(c);
        __syncthreads();
    }

    const int erow = (l >> 2);
    const int ecol = (l & 3) * 2;
    #pragma unroll
    for (int mt = 0; mt < 2; mt++) {
        #pragma unroll
        for (int nt = 0; nt < 8; nt++) {
            int r0 = rowbase + wm * 32 + mt * 16 + erow;
            int c0 = colbase + wn * 64 + nt * 8 + ecol;
            float2 v0 = make_float2(acc[mt][nt][0], acc[mt][nt][1]);
            float2 v1 = make_float2(acc[mt][nt][2], acc[mt][nt][3]);
            if (EPI) {
                float2 x0 = *(const float2*)&X[(size_t)r0 * DM + c0];
                float2 x1 = *(const float2*)&X[(size_t)(r0 + 8) * DM + c0];
                float2 dv = *(const float2*)&Dv[c0];
                v0.x = fmaf(x0.x, dv.x, v0.x); v0.y = fmaf(x0.y, dv.y, v0.y);
                v1.x = fmaf(x1.x, dv.x, v1.x); v1.y = fmaf(x1.y, dv.y, v1.y);
            }
            *(float2*)&Cm[(size_t)r0 * NGLOB + c0]       = v0;
            *(float2*)&Cm[(size_t)(r0 + 8) * NGLOB + c0] = v1;
        }
    }
}

// Wrappers: bind __device__ globals from DEVICE code only.
__global__ void __launch_bounds__(256, 2) gemm1_k() {
    mm_gemm_body<DM, NW1, 3, 2, false>(g_xh, g_xl, g_W1h, nullptr, g_Bu, nullptr, nullptr);
}
__global__ void __launch_bounds__(256, 2) gemm2_k(float* __restrict__ y,
                                                  const float* __restrict__ X,
                                                  const float* __restrict__ Dv) {
    mm_gemm_body<NW1, DM, 2, 3, true>(g_hh, g_hl, g_W2h, g_W2l, y, X, Dv);
}

// ---------------- chunked scan (interleaved: float4 = 2 complex channels) ----
__global__ void scan_carry() {
    int c = blockIdx.x, j = threadIdx.x;
    float2 l0 = g_lam[2 * j], l1 = g_lam[2 * j + 1];
    float4 h = make_float4(0.f, 0.f, 0.f, 0.f);
    const float4* base = (const float4*)(g_Bu + (size_t)c * CHUNK * NW1) + j;
    #pragma unroll 8
    for (int t = 0; t < CHUNK; t++) {
        float4 v = base[(size_t)t * 128];
        float nr0 = fmaf(l0.x, h.x, fmaf(-l0.y, h.y, v.x));
        float ni0 = fmaf(l0.x, h.y, fmaf( l0.y, h.x, v.y));
        float nr1 = fmaf(l1.x, h.z, fmaf(-l1.y, h.w, v.z));
        float ni1 = fmaf(l1.x, h.w, fmaf( l1.y, h.z, v.w));
        h = make_float4(nr0, ni0, nr1, ni1);
    }
    ((float4*)g_carryf)[c * 128 + j] = h;
}

__global__ void chunk_prefix_ks() {
    __shared__ float4 sm[NCHUNK];
    int c = threadIdx.x, j = blockIdx.x;
    float4 x = ((const float4*)g_carryf)[c * 128 + j];
    sm[c] = x;
    __syncthreads();
    #pragma unroll
    for (int s = 0; s < 9; s++) {
        int d = 1 << s;
        float4 pv = make_float4(0.f, 0.f, 0.f, 0.f);
        if (c >= d) pv = sm[c - d];
        float2 p0 = g_lamPow[s * DH + 2 * j];
        float2 p1 = g_lamPow[s * DH + 2 * j + 1];
        __syncthreads();
        if (c >= d) {
            x.x += p0.x * pv.x - p0.y * pv.y;
            x.y += p0.x * pv.y + p0.y * pv.x;
            x.z += p1.x * pv.z - p1.y * pv.w;
            x.w += p1.x * pv.w + p1.y * pv.z;
        }
        sm[c] = x;
        __syncthreads();
    }
    float4 out = make_float4(0.f, 0.f, 0.f, 0.f);
    if (c > 0) out = sm[c - 1];
    ((float4*)g_hinitf)[c * 128 + j] = out;
}

__global__ void scan_apply() {
    int c = blockIdx.x, j = threadIdx.x;
    float2 l0 = g_lam[2 * j], l1 = g_lam[2 * j + 1];
    float4 h = ((const float4*)g_hinitf)[c * 128 + j];
    const float4* base = (const float4*)(g_Bu + (size_t)c * CHUNK * NW1) + j;
    __nv_bfloat16* oh = g_hh + (size_t)c * CHUNK * NW1 + 4 * j;
    __nv_bfloat16* ol = g_hl + (size_t)c * CHUNK * NW1 + 4 * j;
    #pragma unroll 4
    for (int t = 0; t < CHUNK; t++) {
        float4 v = base[(size_t)t * 128];
        float nr0 = fmaf(l0.x, h.x, fmaf(-l0.y, h.y, v.x));
        float ni0 = fmaf(l0.x, h.y, fmaf( l0.y, h.x, v.y));
        float nr1 = fmaf(l1.x, h.z, fmaf(-l1.y, h.w, v.z));
        float ni1 = fmaf(l1.x, h.w, fmaf( l1.y, h.z, v.w));
        h = make_float4(nr0, ni0, nr1, ni1);
        __nv_bfloat16 a0,b0,a1,b1,a2,b2,a3,b3;
        split2(nr0, a0, b0); split2(ni0, a1, b1);
        split2(nr1, a2, b2); split2(ni1, a3, b3);
        __nv_bfloat162 ph0(a0, a1), ph1(a2, a3), pl0(b0, b1), pl1(b2, b3);
        uint2 uh, ul;
        uh.x = *reinterpret_cast<uint32_t*>(&ph0); uh.y = *reinterpret_cast<uint32_t*>(&ph1);
        ul.x = *reinterpret_cast<uint32_t*>(&pl0); ul.y = *reinterpret_cast<uint32_t*>(&pl1);
        *reinterpret_cast<uint2*>(oh + (size_t)t * NW1) = uh;
        *reinterpret_cast<uint2*>(ol + (size_t)t * NW1) = ul;
    }
}

// ---------------- entry ----------------
extern "C" void kernel_launch(void* const* d_in, const int* in_sizes, int n_in,
                              void* d_out, int out_size) {
    const float* x         = (const float*)d_in[0];
    const float* nu_log    = (const float*)d_in[1];
    const float* theta_log = (const float*)d_in[2];
    const float* gamma_log = (const float*)d_in[3];
    const float* B_re      = (const float*)d_in[4];
    const float* B_im      = (const float*)d_in[5];
    const float* C_re      = (const float*)d_in[6];
    const float* C_im      = (const float*)d_in[7];
    const float* Dv        = (const float*)d_in[8];
    float* y = (float*)d_out;

    cudaFuncSetAttribute(gemm1_k, cudaFuncAttributeMaxDynamicSharedMemorySize, SMEM1);
    cudaFuncSetAttribute(gemm2_k, cudaFuncAttributeMaxDynamicSharedMemorySize, SMEM2);

    setup_params<<<1, 256>>>(nu_log, theta_log);
    setup_weights<<<512, 256>>>(gamma_log, B_re, B_im, C_re, C_im);
    split_x<<<(L_SEQ * DM / 4) / 256, 256>>>(x);

    // GEMM1: Bu[L x 512] = x @ W1T^T   (2-term split)
    gemm1_k<<<dim3(NW1 / 128, L_SEQ / 128), 256, SMEM1>>>();

    scan_carry<<<NCHUNK, 128>>>();
    chunk_prefix_ks<<<128, NCHUNK>>>();
    scan_apply<<<NCHUNK, 128>>>();

    // GEMM2: y[L x 256] = h @ W2T^T + x*D   (3-term split)
    gemm2_k<<<dim3(DM / 128, L_SEQ / 128), 256, SMEM2>>>(y, x, Dv);
}

// round 7
// speedup vs baseline: 3.2056x; 1.3709x over previous
#include <cuda_runtime.h>
#include <cuda_fp16.h>
#include <cmath>
#include <cstdint>

#define L_SEQ  32768
#define DM     256
#define DH     256
#define NW1    512
#define CHUNK  64
#define NCHUNK (L_SEQ / CHUNK)   // 512

// ---------------- scratch ----------------
// Channel-interleaved layout: col 2h = re_h, col 2h+1 = im_h.
__device__ float   g_Bu[(size_t)L_SEQ * NW1];     // GEMM1 out (fp32), scan input
__device__ __half  g_xf[(size_t)L_SEQ * DM];      // x in fp16
__device__ __half  g_hf[(size_t)L_SEQ * NW1];     // h in fp16 (scan output)
__device__ __half  g_W1f[NW1 * DM];               // [512][256]
__device__ __half  g_W2f[DM * NW1];               // [256][512]
__device__ float2  g_lam[DH];
__device__ float2  g_lamPow[9 * DH];
__device__ float   g_carryf[NCHUNK * NW1];
__device__ float   g_hinitf[NCHUNK * NW1];

// ---------------- PTX helpers ----------------
__device__ __forceinline__ uint32_t smem_u32(const void* p) {
    uint32_t a;
    asm("{ .reg .u64 t; cvta.to.shared.u64 t, %1; cvt.u32.u64 %0, t; }" : "=r"(a) : "l"(p));
    return a;
}
__device__ __forceinline__ void cp16(uint32_t s, const void* g) {
    asm volatile("cp.async.cg.shared.global [%0], [%1], 16;" :: "r"(s), "l"(g));
}
__device__ __forceinline__ void cp_commit() {
    asm volatile("cp.async.commit_group;" ::: "memory");
}
__device__ __forceinline__ void ldsm4(uint32_t addr, uint32_t* r) {
    asm volatile("ldmatrix.sync.aligned.m8n8.x4.shared.b16 {%0,%1,%2,%3}, [%4];"
                 : "=r"(r[0]), "=r"(r[1]), "=r"(r[2]), "=r"(r[3]) : "r"(addr));
}
__device__ __forceinline__ void mma_f16(float* c, const uint32_t* a, const uint32_t* b) {
    asm volatile("mma.sync.aligned.m16n8k16.row.col.f32.f16.f16.f32 "
                 "{%0,%1,%2,%3},{%4,%5,%6,%7},{%8,%9},{%0,%1,%2,%3};"
                 : "+f"(c[0]), "+f"(c[1]), "+f"(c[2]), "+f"(c[3])
                 : "r"(a[0]), "r"(a[1]), "r"(a[2]), "r"(a[3]), "r"(b[0]), "r"(b[1]));
}

// ---------------- setup ----------------
__global__ void setup_params(const float* __restrict__ nu_log,
                             const float* __restrict__ theta_log) {
    int h = threadIdx.x;
    double nu = exp((double)nu_log[h]);
    double th = exp((double)theta_log[h]);
    double r  = exp(-nu);
    g_lam[h]  = make_float2((float)(r * cos(th)), (float)(r * sin(th)));
    #pragma unroll
    for (int s = 0; s < 9; s++) {
        double sc = (double)CHUNK * (double)(1 << s);
        double rr = exp(-sc * nu);
        double aa = sc * th;
        g_lamPow[s * DH + h] = make_float2((float)(rr * cos(aa)), (float)(rr * sin(aa)));
    }
}

__global__ void setup_weights(const float* __restrict__ gamma_log,
                              const float* __restrict__ B_re,
                              const float* __restrict__ B_im,
                              const float* __restrict__ C_re,
                              const float* __restrict__ C_im) {
    int n = blockIdx.x;   // 0..511 : channel-interleaved (2h=re, 2h+1=im)
    int t = threadIdx.x;  // 0..255
    int h = n >> 1;
    int im = n & 1;
    float g = expf(gamma_log[h]);
    float w = (im ? B_im[h * DM + t] : B_re[h * DM + t]) * g;
    g_W1f[n * DM + t] = __float2half(w);
    float c2 = im ? -C_im[t * DH + h] : C_re[t * DH + h];
    g_W2f[t * NW1 + n] = __float2half(c2);
}

__global__ void cvt_x(const float* __restrict__ x) {
    size_t i = (size_t)blockIdx.x * 256 + threadIdx.x;   // float4 index
    float4 v = ((const float4*)x)[i];
    __half2 p0 = __floats2half2_rn(v.x, v.y);
    __half2 p1 = __floats2half2_rn(v.z, v.w);
    uint2 u;
    u.x = *reinterpret_cast<uint32_t*>(&p0);
    u.y = *reinterpret_cast<uint32_t*>(&p1);
    *reinterpret_cast<uint2*>(g_xf + i * 4) = u;
}

// ---------------- fp16 mma.sync GEMM (single term, 4-stage pipeline) ---------
#define KC      32
#define PITCH   80
#define TILE_B  (128 * PITCH)              // 10240
#define NSTAGE  4
#define STAGE_B (2 * TILE_B)               // A + B tile
#define SMEM_G  (NSTAGE * STAGE_B)         // 81920 per CTA (x2 CTA/SM = 163840)
#define O_A 0
#define O_B TILE_B

template<int KTOT, int NGLOB, bool EPI>
__device__ __forceinline__ void mm_gemm_body(
    const __half* __restrict__ A, const __half* __restrict__ B,
    float* __restrict__ Cm, const float* __restrict__ X, const float* __restrict__ Dv)
{
    extern __shared__ char smem[];
    const uint32_t sb = smem_u32(smem);
    const int tid = threadIdx.x, wid = tid >> 5, l = tid & 31;
    const int rowbase = blockIdx.y * 128;
    const int colbase = blockIdx.x * 128;
    const int wm = wid & 3, wn = wid >> 2;

    float acc[2][8][4];
    #pragma unroll
    for (int i = 0; i < 2; i++)
        #pragma unroll
        for (int j = 0; j < 8; j++)
            #pragma unroll
            for (int q = 0; q < 4; q++) acc[i][j][q] = 0.f;

    const int srow = tid >> 1;
    const int sq   = (tid & 1) * 2;

    auto load_stage = [&](int c) {
        const uint32_t base = sb + (c & (NSTAGE - 1)) * STAGE_B;
        const int k0 = c * KC;
        const __half* gA = A + (size_t)(rowbase + srow) * KTOT + k0;
        const __half* gB = B + (size_t)(colbase + srow) * KTOT + k0;
        #pragma unroll
        for (int d = 0; d < 2; d++) {
            int q = sq + d;
            uint32_t so = srow * PITCH + q * 16;
            cp16(base + O_A + so, gA + q * 8);
            cp16(base + O_B + so, gB + q * 8);
        }
    };

    auto compute = [&](int c) {
        const uint32_t base = sb + (c & (NSTAGE - 1)) * STAGE_B;
        #pragma unroll
        for (int kk = 0; kk < 2; kk++) {
            const int k16 = kk * 16;
            uint32_t av[2][4], bv[4][4];
            const uint32_t arow_off =
                (uint32_t)(wm * 32 + (l & 15)) * PITCH + (uint32_t)(k16 + ((l >> 4) << 3)) * 2;
            const int g = l >> 3;
            const int nadd = ((g & 2) << 2) + (l & 7);
            const int kadd = k16 + ((g & 1) << 3);
            #pragma unroll
            for (int mt = 0; mt < 2; mt++)
                ldsm4(base + O_A + arow_off + (uint32_t)(mt * 16) * PITCH, av[mt]);
            #pragma unroll
            for (int p = 0; p < 4; p++)
                ldsm4(base + O_B + (uint32_t)(wn * 64 + p * 16 + nadd) * PITCH
                           + (uint32_t)kadd * 2, bv[p]);
            #pragma unroll
            for (int mt = 0; mt < 2; mt++)
                #pragma unroll
                for (int nt = 0; nt < 8; nt++)
                    mma_f16(acc[mt][nt], av[mt], &bv[nt >> 1][(nt & 1) * 2]);
        }
    };

    const int NCH = KTOT / KC;
    #pragma unroll
    for (int s = 0; s < NSTAGE - 1; s++) { load_stage(s); cp_commit(); }
    for (int c = 0; c < NCH; c++) {
        if (c + NSTAGE - 1 < NCH) load_stage(c + NSTAGE - 1);
        cp_commit();                       // (possibly empty) group keeps counts uniform
        asm volatile("cp.async.wait_group %0;" :: "n"(NSTAGE - 1) : "memory");
        __syncthreads();
        compute(c);
        __syncthreads();
    }

    const int erow = (l >> 2);
    const int ecol = (l & 3) * 2;
    #pragma unroll
    for (int mt = 0; mt < 2; mt++) {
        #pragma unroll
        for (int nt = 0; nt < 8; nt++) {
            int r0 = rowbase + wm * 32 + mt * 16 + erow;
            int c0 = colbase + wn * 64 + nt * 8 + ecol;
            float2 v0 = make_float2(acc[mt][nt][0], acc[mt][nt][1]);
            float2 v1 = make_float2(acc[mt][nt][2], acc[mt][nt][3]);
            if (EPI) {
                float2 x0 = *(const float2*)&X[(size_t)r0 * DM + c0];
                float2 x1 = *(const float2*)&X[(size_t)(r0 + 8) * DM + c0];
                float2 dv = *(const float2*)&Dv[c0];
                v0.x = fmaf(x0.x, dv.x, v0.x); v0.y = fmaf(x0.y, dv.y, v0.y);
                v1.x = fmaf(x1.x, dv.x, v1.x); v1.y = fmaf(x1.y, dv.y, v1.y);
            }
            *(float2*)&Cm[(size_t)r0 * NGLOB + c0]       = v0;
            *(float2*)&Cm[(size_t)(r0 + 8) * NGLOB + c0] = v1;
        }
    }
}

// Wrappers: bind __device__ globals from DEVICE code only.
__global__ void __launch_bounds__(256, 2) gemm1_k() {
    mm_gemm_body<DM, NW1, false>(g_xf, g_W1f, g_Bu, nullptr, nullptr);
}
__global__ void __launch_bounds__(256, 2) gemm2_k(float* __restrict__ y,
                                                  const float* __restrict__ X,
                                                  const float* __restrict__ Dv) {
    mm_gemm_body<NW1, DM, true>(g_hf, g_W2f, y, X, Dv);
}

// ---------------- chunked scan (interleaved: float4 = 2 complex channels) ----
__global__ void scan_carry() {
    int c = blockIdx.x, j = threadIdx.x;
    float2 l0 = g_lam[2 * j], l1 = g_lam[2 * j + 1];
    float4 h = make_float4(0.f, 0.f, 0.f, 0.f);
    const float4* base = (const float4*)(g_Bu + (size_t)c * CHUNK * NW1) + j;
    #pragma unroll 8
    for (int t = 0; t < CHUNK; t++) {
        float4 v = base[(size_t)t * 128];
        float nr0 = fmaf(l0.x, h.x, fmaf(-l0.y, h.y, v.x));
        float ni0 = fmaf(l0.x, h.y, fmaf( l0.y, h.x, v.y));
        float nr1 = fmaf(l1.x, h.z, fmaf(-l1.y, h.w, v.z));
        float ni1 = fmaf(l1.x, h.w, fmaf( l1.y, h.z, v.w));
        h = make_float4(nr0, ni0, nr1, ni1);
    }
    ((float4*)g_carryf)[c * 128 + j] = h;
}

__global__ void chunk_prefix_ks() {
    __shared__ float4 sm[NCHUNK];
    int c = threadIdx.x, j = blockIdx.x;
    float4 x = ((const float4*)g_carryf)[c * 128 + j];
    sm[c] = x;
    __syncthreads();
    #pragma unroll
    for (int s = 0; s < 9; s++) {
        int d = 1 << s;
        float4 pv = make_float4(0.f, 0.f, 0.f, 0.f);
        if (c >= d) pv = sm[c - d];
        float2 p0 = g_lamPow[s * DH + 2 * j];
        float2 p1 = g_lamPow[s * DH + 2 * j + 1];
        __syncthreads();
        if (c >= d) {
            x.x += p0.x * pv.x - p0.y * pv.y;
            x.y += p0.x * pv.y + p0.y * pv.x;
            x.z += p1.x * pv.z - p1.y * pv.w;
            x.w += p1.x * pv.w + p1.y * pv.z;
        }
        sm[c] = x;
        __syncthreads();
    }
    float4 out = make_float4(0.f, 0.f, 0.f, 0.f);
    if (c > 0) out = sm[c - 1];
    ((float4*)g_hinitf)[c * 128 + j] = out;
}

__global__ void scan_apply() {
    int c = blockIdx.x, j = threadIdx.x;
    float2 l0 = g_lam[2 * j], l1 = g_lam[2 * j + 1];
    float4 h = ((const float4*)g_hinitf)[c * 128 + j];
    const float4* base = (const float4*)(g_Bu + (size_t)c * CHUNK * NW1) + j;
    __half* of = g_hf + (size_t)c * CHUNK * NW1 + 4 * j;
    #pragma unroll 4
    for (int t = 0; t < CHUNK; t++) {
        float4 v = base[(size_t)t * 128];
        float nr0 = fmaf(l0.x, h.x, fmaf(-l0.y, h.y, v.x));
        float ni0 = fmaf(l0.x, h.y, fmaf( l0.y, h.x, v.y));
        float nr1 = fmaf(l1.x, h.z, fmaf(-l1.y, h.w, v.z));
        float ni1 = fmaf(l1.x, h.w, fmaf( l1.y, h.z, v.w));
        h = make_float4(nr0, ni0, nr1, ni1);
        __half2 p0 = __floats2half2_rn(nr0, ni0);
        __half2 p1 = __floats2half2_rn(nr1, ni1);
        uint2 u;
        u.x = *reinterpret_cast<uint32_t*>(&p0);
        u.y = *reinterpret_cast<uint32_t*>(&p1);
        *reinterpret_cast<uint2*>(of + (size_t)t * NW1) = u;
    }
}

// ---------------- entry ----------------
extern "C" void kernel_launch(void* const* d_in, const int* in_sizes, int n_in,
                              void* d_out, int out_size) {
    const float* x         = (const float*)d_in[0];
    const float* nu_log    = (const float*)d_in[1];
    const float* theta_log = (const float*)d_in[2];
    const float* gamma_log = (const float*)d_in[3];
    const float* B_re      = (const float*)d_in[4];
    const float* B_im      = (const float*)d_in[5];
    const float* C_re      = (const float*)d_in[6];
    const float* C_im      = (const float*)d_in[7];
    const float* Dv        = (const float*)d_in[8];
    float* y = (float*)d_out;

    cudaFuncSetAttribute(gemm1_k, cudaFuncAttributeMaxDynamicSharedMemorySize, SMEM_G);
    cudaFuncSetAttribute(gemm2_k, cudaFuncAttributeMaxDynamicSharedMemorySize, SMEM_G);

    setup_params<<<1, 256>>>(nu_log, theta_log);
    setup_weights<<<512, 256>>>(gamma_log, B_re, B_im, C_re, C_im);
    cvt_x<<<(L_SEQ * DM / 4) / 256, 256>>>(x);

    // GEMM1: Bu[L x 512] = x @ W1T^T   (fp16 single-term)
    gemm1_k<<<dim3(NW1 / 128, L_SEQ / 128), 256, SMEM_G>>>();

    scan_carry<<<NCHUNK, 128>>>();
    chunk_prefix_ks<<<128, NCHUNK>>>();
    scan_apply<<<NCHUNK, 128>>>();

    // GEMM2: y[L x 256] = h @ W2T^T + x*D   (fp16 single-term)
    gemm2_k<<<dim3(DM / 128, L_SEQ / 128), 256, SMEM_G>>>(y, x, Dv);
}

// round 8
// speedup vs baseline: 3.4417x; 1.0737x over previous
#include <cuda_runtime.h>
#include <cuda_fp16.h>
#include <cmath>
#include <cstdint>

#define L_SEQ  32768
#define DM     256
#define DH     256
#define NW1    512
#define CHUNK  64
#define NCHUNK (L_SEQ / CHUNK)   // 512

// ---------------- scratch ----------------
// Channel-interleaved layout: col 2h = re_h, col 2h+1 = im_h.
__device__ __half  g_BuH[(size_t)L_SEQ * NW1];    // GEMM1 out (fp16), scan input
__device__ __half  g_xf[(size_t)L_SEQ * DM];      // x in fp16
__device__ __half  g_hf[(size_t)L_SEQ * NW1];     // h in fp16 (scan output)
__device__ __half  g_W1f[NW1 * DM];               // [512][256]
__device__ __half  g_W2f[DM * NW1];               // [256][512]
__device__ float2  g_lam[DH];
__device__ float2  g_lamPow[9 * DH];
__device__ float   g_carryf[NCHUNK * NW1];
__device__ float   g_hinitf[NCHUNK * NW1];

// ---------------- PTX helpers ----------------
__device__ __forceinline__ uint32_t smem_u32(const void* p) {
    uint32_t a;
    asm("{ .reg .u64 t; cvta.to.shared.u64 t, %1; cvt.u32.u64 %0, t; }" : "=r"(a) : "l"(p));
    return a;
}
__device__ __forceinline__ void cp16(uint32_t s, const void* g) {
    asm volatile("cp.async.cg.shared.global [%0], [%1], 16;" :: "r"(s), "l"(g));
}
__device__ __forceinline__ void cp_commit() {
    asm volatile("cp.async.commit_group;" ::: "memory");
}
__device__ __forceinline__ void ldsm4(uint32_t addr, uint32_t* r) {
    asm volatile("ldmatrix.sync.aligned.m8n8.x4.shared.b16 {%0,%1,%2,%3}, [%4];"
                 : "=r"(r[0]), "=r"(r[1]), "=r"(r[2]), "=r"(r[3]) : "r"(addr));
}
__device__ __forceinline__ void mma_f16(float* c, const uint32_t* a, const uint32_t* b) {
    asm volatile("mma.sync.aligned.m16n8k16.row.col.f32.f16.f16.f32 "
                 "{%0,%1,%2,%3},{%4,%5,%6,%7},{%8,%9},{%0,%1,%2,%3};"
                 : "+f"(c[0]), "+f"(c[1]), "+f"(c[2]), "+f"(c[3])
                 : "r"(a[0]), "r"(a[1]), "r"(a[2]), "r"(a[3]), "r"(b[0]), "r"(b[1]));
}

// ---------------- setup ----------------
__global__ void setup_params(const float* __restrict__ nu_log,
                             const float* __restrict__ theta_log) {
    int h = threadIdx.x;
    double nu = exp((double)nu_log[h]);
    double th = exp((double)theta_log[h]);
    double r  = exp(-nu);
    g_lam[h]  = make_float2((float)(r * cos(th)), (float)(r * sin(th)));
    #pragma unroll
    for (int s = 0; s < 9; s++) {
        double sc = (double)CHUNK * (double)(1 << s);
        double rr = exp(-sc * nu);
        double aa = sc * th;
        g_lamPow[s * DH + h] = make_float2((float)(rr * cos(aa)), (float)(rr * sin(aa)));
    }
}

__global__ void setup_weights(const float* __restrict__ gamma_log,
                              const float* __restrict__ B_re,
                              const float* __restrict__ B_im,
                              const float* __restrict__ C_re,
                              const float* __restrict__ C_im) {
    int n = blockIdx.x;   // 0..511 : channel-interleaved (2h=re, 2h+1=im)
    int t = threadIdx.x;  // 0..255
    int h = n >> 1;
    int im = n & 1;
    float g = expf(gamma_log[h]);
    float w = (im ? B_im[h * DM + t] : B_re[h * DM + t]) * g;
    g_W1f[n * DM + t] = __float2half(w);
    float c2 = im ? -C_im[t * DH + h] : C_re[t * DH + h];
    g_W2f[t * NW1 + n] = __float2half(c2);
}

__global__ void cvt_x(const float* __restrict__ x) {
    size_t i = (size_t)blockIdx.x * 256 + threadIdx.x;   // float4 index
    float4 v = ((const float4*)x)[i];
    __half2 p0 = __floats2half2_rn(v.x, v.y);
    __half2 p1 = __floats2half2_rn(v.z, v.w);
    uint2 u;
    u.x = *reinterpret_cast<uint32_t*>(&p0);
    u.y = *reinterpret_cast<uint32_t*>(&p1);
    *reinterpret_cast<uint2*>(g_xf + i * 4) = u;
}

// ---------------- fp16 mma.sync GEMM (single term, 4-stage pipeline) ---------
#define KC      32
#define PITCH   80
#define TILE_B  (128 * PITCH)              // 10240
#define NSTAGE  4
#define STAGE_B (2 * TILE_B)               // A + B tile
#define SMEM_G  (NSTAGE * STAGE_B)         // 81920 per CTA (x2 CTA/SM)
#define O_A 0
#define O_B TILE_B

// FUSE_SCAN: epilogue stashes fp16 tile in smem, runs 2x 64-step local scans,
// writes per-chunk carries (gemm1 only).
template<int KTOT, int NGLOB, bool EPI, bool FUSE_SCAN, bool HALF_OUT>
__device__ __forceinline__ void mm_gemm_body(
    const __half* __restrict__ A, const __half* __restrict__ B,
    void* __restrict__ Cm, const float* __restrict__ X, const float* __restrict__ Dv)
{
    extern __shared__ char smem[];
    const uint32_t sb = smem_u32(smem);
    const int tid = threadIdx.x, wid = tid >> 5, l = tid & 31;
    const int rowbase = blockIdx.y * 128;
    const int colbase = blockIdx.x * 128;
    const int wm = wid & 3, wn = wid >> 2;

    float acc[2][8][4];
    #pragma unroll
    for (int i = 0; i < 2; i++)
        #pragma unroll
        for (int j = 0; j < 8; j++)
            #pragma unroll
            for (int q = 0; q < 4; q++) acc[i][j][q] = 0.f;

    const int srow = tid >> 1;
    const int sq   = (tid & 1) * 2;

    auto load_stage = [&](int c) {
        const uint32_t base = sb + (c & (NSTAGE - 1)) * STAGE_B;
        const int k0 = c * KC;
        const __half* gA = A + (size_t)(rowbase + srow) * KTOT + k0;
        const __half* gB = B + (size_t)(colbase + srow) * KTOT + k0;
        #pragma unroll
        for (int d = 0; d < 2; d++) {
            int q = sq + d;
            uint32_t so = srow * PITCH + q * 16;
            cp16(base + O_A + so, gA + q * 8);
            cp16(base + O_B + so, gB + q * 8);
        }
    };

    auto compute = [&](int c) {
        const uint32_t base = sb + (c & (NSTAGE - 1)) * STAGE_B;
        #pragma unroll
        for (int kk = 0; kk < 2; kk++) {
            const int k16 = kk * 16;
            uint32_t av[2][4], bv[4][4];
            const uint32_t arow_off =
                (uint32_t)(wm * 32 + (l & 15)) * PITCH + (uint32_t)(k16 + ((l >> 4) << 3)) * 2;
            const int g = l >> 3;
            const int nadd = ((g & 2) << 2) + (l & 7);
            const int kadd = k16 + ((g & 1) << 3);
            #pragma unroll
            for (int mt = 0; mt < 2; mt++)
                ldsm4(base + O_A + arow_off + (uint32_t)(mt * 16) * PITCH, av[mt]);
            #pragma unroll
            for (int p = 0; p < 4; p++)
                ldsm4(base + O_B + (uint32_t)(wn * 64 + p * 16 + nadd) * PITCH
                           + (uint32_t)kadd * 2, bv[p]);
            #pragma unroll
            for (int mt = 0; mt < 2; mt++)
                #pragma unroll
                for (int nt = 0; nt < 8; nt++)
                    mma_f16(acc[mt][nt], av[mt], &bv[nt >> 1][(nt & 1) * 2]);
        }
    };

    const int NCH = KTOT / KC;
    #pragma unroll
    for (int s = 0; s < NSTAGE - 1; s++) { load_stage(s); cp_commit(); }
    for (int c = 0; c < NCH; c++) {
        if (c + NSTAGE - 1 < NCH) load_stage(c + NSTAGE - 1);
        cp_commit();
        asm volatile("cp.async.wait_group %0;" :: "n"(NSTAGE - 1) : "memory");
        __syncthreads();
        compute(c);
        __syncthreads();
    }
    // smem pipeline fully consumed past this point (last sync above)

    const int erow = (l >> 2);
    const int ecol = (l & 3) * 2;
    #pragma unroll
    for (int mt = 0; mt < 2; mt++) {
        #pragma unroll
        for (int nt = 0; nt < 8; nt++) {
            int rl = wm * 32 + mt * 16 + erow;        // CTA-local row
            int cl = wn * 64 + nt * 8 + ecol;         // CTA-local col (even)
            int r0 = rowbase + rl;
            int c0 = colbase + cl;
            float2 v0 = make_float2(acc[mt][nt][0], acc[mt][nt][1]);
            float2 v1 = make_float2(acc[mt][nt][2], acc[mt][nt][3]);
            if (EPI) {
                float2 x0 = *(const float2*)&X[(size_t)r0 * DM + c0];
                float2 x1 = *(const float2*)&X[(size_t)(r0 + 8) * DM + c0];
                float2 dv = *(const float2*)&Dv[c0];
                v0.x = fmaf(x0.x, dv.x, v0.x); v0.y = fmaf(x0.y, dv.y, v0.y);
                v1.x = fmaf(x1.x, dv.x, v1.x); v1.y = fmaf(x1.y, dv.y, v1.y);
            }
            if (HALF_OUT) {
                __half2 q0 = __floats2half2_rn(v0.x, v0.y);
                __half2 q1 = __floats2half2_rn(v1.x, v1.y);
                __half* C = (__half*)Cm;
                *(__half2*)&C[(size_t)r0 * NGLOB + c0]       = q0;
                *(__half2*)&C[(size_t)(r0 + 8) * NGLOB + c0] = q1;
                if (FUSE_SCAN) {   // stash fp16 tile (pitch 256B per row)
                    *(uint32_t*)(smem + rl * 256 + cl * 2)       = *(uint32_t*)&q0;
                    *(uint32_t*)(smem + (rl + 8) * 256 + cl * 2) = *(uint32_t*)&q1;
                }
            } else {
                float* C = (float*)Cm;
                *(float2*)&C[(size_t)r0 * NGLOB + c0]       = v0;
                *(float2*)&C[(size_t)(r0 + 8) * NGLOB + c0] = v1;
            }
        }
    }

    if (FUSE_SCAN) {
        __syncthreads();
        if (tid < 128) {
            int ch = tid & 63;          // CTA-local complex channel (0..63)
            int ck = tid >> 6;          // sub-chunk (0 or 1): rows [64ck, 64ck+64)
            float2 lam = g_lam[(colbase >> 1) + ch];
            float hr = 0.f, hi = 0.f;
            const char* sp = smem + ck * 64 * 256 + ch * 4;
            #pragma unroll 8
            for (int t = 0; t < 64; t++) {
                uint32_t u = *(const uint32_t*)(sp + t * 256);
                __half2 hv = *(__half2*)&u;
                float br = __low2float(hv), bi = __high2float(hv);
                float nr = fmaf(lam.x, hr, fmaf(-lam.y, hi, br));
                float ni = fmaf(lam.x, hi, fmaf( lam.y, hr, bi));
                hr = nr; hi = ni;
            }
            int chunk = blockIdx.y * 2 + ck;
            *(float2*)&g_carryf[(size_t)chunk * NW1 + colbase + 2 * ch] =
                make_float2(hr, hi);
        }
    }
}

// Wrappers: bind __device__ globals from DEVICE code only.
__global__ void __launch_bounds__(256, 2) gemm1_k() {
    mm_gemm_body<DM, NW1, false, true, true>(g_xf, g_W1f, g_BuH, nullptr, nullptr);
}
__global__ void __launch_bounds__(256, 2) gemm2_k(float* __restrict__ y,
                                                  const float* __restrict__ X,
                                                  const float* __restrict__ Dv) {
    mm_gemm_body<NW1, DM, true, false, false>(g_hf, g_W2f, y, X, Dv);
}

// ---------------- chunk prefix (Kogge-Stone over 512 chunks) -----------------
__global__ void chunk_prefix_ks() {
    __shared__ float4 sm[NCHUNK];
    int c = threadIdx.x, j = blockIdx.x;   // j: channel pair 0..127
    float4 x = ((const float4*)g_carryf)[c * 128 + j];
    sm[c] = x;
    __syncthreads();
    #pragma unroll
    for (int s = 0; s < 9; s++) {
        int d = 1 << s;
        float4 pv = make_float4(0.f, 0.f, 0.f, 0.f);
        if (c >= d) pv = sm[c - d];
        float2 p0 = g_lamPow[s * DH + 2 * j];
        float2 p1 = g_lamPow[s * DH + 2 * j + 1];
        __syncthreads();
        if (c >= d) {
            x.x += p0.x * pv.x - p0.y * pv.y;
            x.y += p0.x * pv.y + p0.y * pv.x;
            x.z += p1.x * pv.z - p1.y * pv.w;
            x.w += p1.x * pv.w + p1.y * pv.z;
        }
        sm[c] = x;
        __syncthreads();
    }
    float4 out = make_float4(0.f, 0.f, 0.f, 0.f);
    if (c > 0) out = sm[c - 1];
    ((float4*)g_hinitf)[c * 128 + j] = out;
}

// ---------------- scan_apply: fp16 Bu -> fp16 h ------------------------------
__global__ void scan_apply() {
    int c = blockIdx.x, j = threadIdx.x;   // j: 0..127, 2 complex channels each
    float2 l0 = g_lam[2 * j], l1 = g_lam[2 * j + 1];
    float4 h = ((const float4*)g_hinitf)[c * 128 + j];
    const uint2* base = (const uint2*)(g_BuH + (size_t)c * CHUNK * NW1) + j;
    __half* of = g_hf + (size_t)c * CHUNK * NW1 + 4 * j;
    #pragma unroll 4
    for (int t = 0; t < CHUNK; t++) {
        uint2 u = base[(size_t)t * 128];
        __half2 b0 = *(__half2*)&u.x;
        __half2 b1 = *(__half2*)&u.y;
        float nr0 = fmaf(l0.x, h.x, fmaf(-l0.y, h.y, __low2float(b0)));
        float ni0 = fmaf(l0.x, h.y, fmaf( l0.y, h.x, __high2float(b0)));
        float nr1 = fmaf(l1.x, h.z, fmaf(-l1.y, h.w, __low2float(b1)));
        float ni1 = fmaf(l1.x, h.w, fmaf( l1.y, h.z, __high2float(b1)));
        h = make_float4(nr0, ni0, nr1, ni1);
        __half2 p0 = __floats2half2_rn(nr0, ni0);
        __half2 p1 = __floats2half2_rn(nr1, ni1);
        uint2 o;
        o.x = *reinterpret_cast<uint32_t*>(&p0);
        o.y = *reinterpret_cast<uint32_t*>(&p1);
        *reinterpret_cast<uint2*>(of + (size_t)t * NW1) = o;
    }
}

// ---------------- entry ----------------
extern "C" void kernel_launch(void* const* d_in, const int* in_sizes, int n_in,
                              void* d_out, int out_size) {
    const float* x         = (const float*)d_in[0];
    const float* nu_log    = (const float*)d_in[1];
    const float* theta_log = (const float*)d_in[2];
    const float* gamma_log = (const float*)d_in[3];
    const float* B_re      = (const float*)d_in[4];
    const float* B_im      = (const float*)d_in[5];
    const float* C_re      = (const float*)d_in[6];
    const float* C_im      = (const float*)d_in[7];
    const float* Dv        = (const float*)d_in[8];
    float* y = (float*)d_out;

    cudaFuncSetAttribute(gemm1_k, cudaFuncAttributeMaxDynamicSharedMemorySize, SMEM_G);
    cudaFuncSetAttribute(gemm2_k, cudaFuncAttributeMaxDynamicSharedMemorySize, SMEM_G);

    setup_params<<<1, 256>>>(nu_log, theta_log);
    setup_weights<<<512, 256>>>(gamma_log, B_re, B_im, C_re, C_im);
    cvt_x<<<(L_SEQ * DM / 4) / 256, 256>>>(x);

    // GEMM1 (+ fused per-chunk carry scan): BuH = x @ W1T^T
    gemm1_k<<<dim3(NW1 / 128, L_SEQ / 128), 256, SMEM_G>>>();

    chunk_prefix_ks<<<128, NCHUNK>>>();
    scan_apply<<<NCHUNK, 128>>>();

    // GEMM2: y = h @ W2T^T + x*D
    gemm2_k<<<dim3(DM / 128, L_SEQ / 128), 256, SMEM_G>>>(y, x, Dv);
}

// round 9
// speedup vs baseline: 3.4986x; 1.0165x over previous
#include <cuda_runtime.h>
#include <cuda_fp16.h>
#include <cmath>
#include <cstdint>

#define L_SEQ  32768
#define DM     256
#define DH     256
#define NW1    512
#define CHUNK  32
#define NCHUNK (L_SEQ / CHUNK)   // 1024
#define NPOW   10                // KS stages: 2^10 = 1024

// ---------------- scratch ----------------
// Channel-interleaved layout: col 2h = re_h, col 2h+1 = im_h.
__device__ __half  g_BuH[(size_t)L_SEQ * NW1];    // GEMM1 out (fp16), scan input
__device__ __half  g_xf[(size_t)L_SEQ * DM];      // x in fp16
__device__ __half  g_hf[(size_t)L_SEQ * NW1];     // h in fp16 (scan output)
__device__ __half  g_W1f[NW1 * DM];               // [512][256]
__device__ __half  g_W2f[DM * NW1];               // [256][512]
__device__ float2  g_lam[DH];
__device__ float2  g_lamPow[NPOW * DH];           // (lambda^CHUNK)^(2^s)
__device__ float   g_carryf[(size_t)NCHUNK * NW1];
__device__ float   g_hinitf[(size_t)NCHUNK * NW1];

// ---------------- PTX helpers ----------------
__device__ __forceinline__ uint32_t smem_u32(const void* p) {
    uint32_t a;
    asm("{ .reg .u64 t; cvta.to.shared.u64 t, %1; cvt.u32.u64 %0, t; }" : "=r"(a) : "l"(p));
    return a;
}
__device__ __forceinline__ void cp16(uint32_t s, const void* g) {
    asm volatile("cp.async.cg.shared.global [%0], [%1], 16;" :: "r"(s), "l"(g));
}
__device__ __forceinline__ void cp_commit() {
    asm volatile("cp.async.commit_group;" ::: "memory");
}
__device__ __forceinline__ void ldsm4(uint32_t addr, uint32_t* r) {
    asm volatile("ldmatrix.sync.aligned.m8n8.x4.shared.b16 {%0,%1,%2,%3}, [%4];"
                 : "=r"(r[0]), "=r"(r[1]), "=r"(r[2]), "=r"(r[3]) : "r"(addr));
}
__device__ __forceinline__ void mma_f16(float* c, const uint32_t* a, const uint32_t* b) {
    asm volatile("mma.sync.aligned.m16n8k16.row.col.f32.f16.f16.f32 "
                 "{%0,%1,%2,%3},{%4,%5,%6,%7},{%8,%9},{%0,%1,%2,%3};"
                 : "+f"(c[0]), "+f"(c[1]), "+f"(c[2]), "+f"(c[3])
                 : "r"(a[0]), "r"(a[1]), "r"(a[2]), "r"(a[3]), "r"(b[0]), "r"(b[1]));
}

// ---------------- setup ----------------
__global__ void setup_params(const float* __restrict__ nu_log,
                             const float* __restrict__ theta_log) {
    int h = threadIdx.x;
    double nu = exp((double)nu_log[h]);
    double th = exp((double)theta_log[h]);
    double r  = exp(-nu);
    g_lam[h]  = make_float2((float)(r * cos(th)), (float)(r * sin(th)));
    #pragma unroll
    for (int s = 0; s < NPOW; s++) {
        double sc = (double)CHUNK * (double)(1 << s);
        double rr = exp(-sc * nu);
        double aa = sc * th;
        g_lamPow[s * DH + h] = make_float2((float)(rr * cos(aa)), (float)(rr * sin(aa)));
    }
}

__global__ void setup_weights(const float* __restrict__ gamma_log,
                              const float* __restrict__ B_re,
                              const float* __restrict__ B_im,
                              const float* __restrict__ C_re,
                              const float* __restrict__ C_im) {
    int n = blockIdx.x;   // 0..511 : channel-interleaved (2h=re, 2h+1=im)
    int t = threadIdx.x;  // 0..255
    int h = n >> 1;
    int im = n & 1;
    float g = expf(gamma_log[h]);
    float w = (im ? B_im[h * DM + t] : B_re[h * DM + t]) * g;
    g_W1f[n * DM + t] = __float2half(w);
    float c2 = im ? -C_im[t * DH + h] : C_re[t * DH + h];
    g_W2f[t * NW1 + n] = __float2half(c2);
}

__global__ void cvt_x(const float* __restrict__ x) {
    size_t i = (size_t)blockIdx.x * 256 + threadIdx.x;   // float4 index
    float4 v = ((const float4*)x)[i];
    __half2 p0 = __floats2half2_rn(v.x, v.y);
    __half2 p1 = __floats2half2_rn(v.z, v.w);
    uint2 u;
    u.x = *reinterpret_cast<uint32_t*>(&p0);
    u.y = *reinterpret_cast<uint32_t*>(&p1);
    *reinterpret_cast<uint2*>(g_xf + i * 4) = u;
}

// ---------------- fp16 mma.sync GEMM (single term, 4-stage pipeline) ---------
#define KC      32
#define PITCH   80
#define TILE_B  (128 * PITCH)              // 10240
#define NSTAGE  4
#define STAGE_B (2 * TILE_B)               // A + B tile
#define SMEM_G  (NSTAGE * STAGE_B)         // 81920 per CTA (x2 CTA/SM)
#define O_A 0
#define O_B TILE_B

// FUSE_SCAN: epilogue stashes fp16 tile in smem, runs 4x 32-step local scans
// with ALL 256 threads, writes per-chunk carries (gemm1 only).
template<int KTOT, int NGLOB, bool EPI, bool FUSE_SCAN, bool HALF_OUT>
__device__ __forceinline__ void mm_gemm_body(
    const __half* __restrict__ A, const __half* __restrict__ B,
    void* __restrict__ Cm, const float* __restrict__ X, const float* __restrict__ Dv)
{
    extern __shared__ char smem[];
    const uint32_t sb = smem_u32(smem);
    const int tid = threadIdx.x, wid = tid >> 5, l = tid & 31;
    const int rowbase = blockIdx.y * 128;
    const int colbase = blockIdx.x * 128;
    const int wm = wid & 3, wn = wid >> 2;

    float acc[2][8][4];
    #pragma unroll
    for (int i = 0; i < 2; i++)
        #pragma unroll
        for (int j = 0; j < 8; j++)
            #pragma unroll
            for (int q = 0; q < 4; q++) acc[i][j][q] = 0.f;

    const int srow = tid >> 1;
    const int sq   = (tid & 1) * 2;

    auto load_stage = [&](int c) {
        const uint32_t base = sb + (c & (NSTAGE - 1)) * STAGE_B;
        const int k0 = c * KC;
        const __half* gA = A + (size_t)(rowbase + srow) * KTOT + k0;
        const __half* gB = B + (size_t)(colbase + srow) * KTOT + k0;
        #pragma unroll
        for (int d = 0; d < 2; d++) {
            int q = sq + d;
            uint32_t so = srow * PITCH + q * 16;
            cp16(base + O_A + so, gA + q * 8);
            cp16(base + O_B + so, gB + q * 8);
        }
    };

    auto compute = [&](int c) {
        const uint32_t base = sb + (c & (NSTAGE - 1)) * STAGE_B;
        #pragma unroll
        for (int kk = 0; kk < 2; kk++) {
            const int k16 = kk * 16;
            uint32_t av[2][4], bv[4][4];
            const uint32_t arow_off =
                (uint32_t)(wm * 32 + (l & 15)) * PITCH + (uint32_t)(k16 + ((l >> 4) << 3)) * 2;
            const int g = l >> 3;
            const int nadd = ((g & 2) << 2) + (l & 7);
            const int kadd = k16 + ((g & 1) << 3);
            #pragma unroll
            for (int mt = 0; mt < 2; mt++)
                ldsm4(base + O_A + arow_off + (uint32_t)(mt * 16) * PITCH, av[mt]);
            #pragma unroll
            for (int p = 0; p < 4; p++)
                ldsm4(base + O_B + (uint32_t)(wn * 64 + p * 16 + nadd) * PITCH
                           + (uint32_t)kadd * 2, bv[p]);
            #pragma unroll
            for (int mt = 0; mt < 2; mt++)
                #pragma unroll
                for (int nt = 0; nt < 8; nt++)
                    mma_f16(acc[mt][nt], av[mt], &bv[nt >> 1][(nt & 1) * 2]);
        }
    };

    const int NCH = KTOT / KC;
    #pragma unroll
    for (int s = 0; s < NSTAGE - 1; s++) { load_stage(s); cp_commit(); }
    for (int c = 0; c < NCH; c++) {
        if (c + NSTAGE - 1 < NCH) load_stage(c + NSTAGE - 1);
        cp_commit();
        asm volatile("cp.async.wait_group %0;" :: "n"(NSTAGE - 1) : "memory");
        __syncthreads();
        compute(c);
        __syncthreads();
    }
    // smem pipeline fully consumed past this point

    const int erow = (l >> 2);
    const int ecol = (l & 3) * 2;
    #pragma unroll
    for (int mt = 0; mt < 2; mt++) {
        #pragma unroll
        for (int nt = 0; nt < 8; nt++) {
            int rl = wm * 32 + mt * 16 + erow;        // CTA-local row
            int cl = wn * 64 + nt * 8 + ecol;         // CTA-local col (even)
            int r0 = rowbase + rl;
            int c0 = colbase + cl;
            float2 v0 = make_float2(acc[mt][nt][0], acc[mt][nt][1]);
            float2 v1 = make_float2(acc[mt][nt][2], acc[mt][nt][3]);
            if (EPI) {
                float2 x0 = *(const float2*)&X[(size_t)r0 * DM + c0];
                float2 x1 = *(const float2*)&X[(size_t)(r0 + 8) * DM + c0];
                float2 dv = *(const float2*)&Dv[c0];
                v0.x = fmaf(x0.x, dv.x, v0.x); v0.y = fmaf(x0.y, dv.y, v0.y);
                v1.x = fmaf(x1.x, dv.x, v1.x); v1.y = fmaf(x1.y, dv.y, v1.y);
            }
            if (HALF_OUT) {
                __half2 q0 = __floats2half2_rn(v0.x, v0.y);
                __half2 q1 = __floats2half2_rn(v1.x, v1.y);
                __half* C = (__half*)Cm;
                *(__half2*)&C[(size_t)r0 * NGLOB + c0]       = q0;
                *(__half2*)&C[(size_t)(r0 + 8) * NGLOB + c0] = q1;
                if (FUSE_SCAN) {   // stash fp16 tile (pitch 256B per row)
                    *(uint32_t*)(smem + rl * 256 + cl * 2)       = *(uint32_t*)&q0;
                    *(uint32_t*)(smem + (rl + 8) * 256 + cl * 2) = *(uint32_t*)&q1;
                }
            } else {
                float* C = (float*)Cm;
                *(float2*)&C[(size_t)r0 * NGLOB + c0]       = v0;
                *(float2*)&C[(size_t)(r0 + 8) * NGLOB + c0] = v1;
            }
        }
    }

    if (FUSE_SCAN) {
        __syncthreads();
        // 4 sub-chunks of 32 rows x 64 complex channels -> 256 independent scans
        int ch = tid & 63;          // CTA-local complex channel (0..63)
        int ck = tid >> 6;          // sub-chunk (0..3): rows [32ck, 32ck+32)
        float2 lam = g_lam[(colbase >> 1) + ch];
        float hr = 0.f, hi = 0.f;
        const char* sp = smem + ck * 32 * 256 + ch * 4;
        #pragma unroll 8
        for (int t = 0; t < CHUNK; t++) {
            uint32_t u = *(const uint32_t*)(sp + t * 256);
            __half2 hv = *(__half2*)&u;
            float br = __low2float(hv), bi = __high2float(hv);
            float nr = fmaf(lam.x, hr, fmaf(-lam.y, hi, br));
            float ni = fmaf(lam.x, hi, fmaf( lam.y, hr, bi));
            hr = nr; hi = ni;
        }
        int chunk = blockIdx.y * 4 + ck;
        *(float2*)&g_carryf[(size_t)chunk * NW1 + colbase + 2 * ch] =
            make_float2(hr, hi);
    }
}

// Wrappers: bind __device__ globals from DEVICE code only.
__global__ void __launch_bounds__(256, 2) gemm1_k() {
    mm_gemm_body<DM, NW1, false, true, true>(g_xf, g_W1f, g_BuH, nullptr, nullptr);
}
__global__ void __launch_bounds__(256, 2) gemm2_k(float* __restrict__ y,
                                                  const float* __restrict__ X,
                                                  const float* __restrict__ Dv) {
    mm_gemm_body<NW1, DM, true, false, false>(g_hf, g_W2f, y, X, Dv);
}

// ---------------- chunk prefix (Kogge-Stone over 1024 chunks) ----------------
__global__ void __launch_bounds__(NCHUNK) chunk_prefix_ks() {
    __shared__ float4 sm[NCHUNK];
    int c = threadIdx.x, j = blockIdx.x;   // j: channel pair 0..127
    float4 x = ((const float4*)g_carryf)[(size_t)c * 128 + j];
    sm[c] = x;
    __syncthreads();
    #pragma unroll
    for (int s = 0; s < NPOW; s++) {
        int d = 1 << s;
        float4 pv = make_float4(0.f, 0.f, 0.f, 0.f);
        if (c >= d) pv = sm[c - d];
        float2 p0 = g_lamPow[s * DH + 2 * j];
        float2 p1 = g_lamPow[s * DH + 2 * j + 1];
        __syncthreads();
        if (c >= d) {
            x.x += p0.x * pv.x - p0.y * pv.y;
            x.y += p0.x * pv.y + p0.y * pv.x;
            x.z += p1.x * pv.z - p1.y * pv.w;
            x.w += p1.x * pv.w + p1.y * pv.z;
        }
        sm[c] = x;
        __syncthreads();
    }
    float4 out = make_float4(0.f, 0.f, 0.f, 0.f);
    if (c > 0) out = sm[c - 1];
    ((float4*)g_hinitf)[(size_t)c * 128 + j] = out;
}

// ---------------- scan_apply: fp16 Bu -> fp16 h ------------------------------
__global__ void scan_apply() {
    int c = blockIdx.x, j = threadIdx.x;   // j: 0..127, 2 complex channels each
    float2 l0 = g_lam[2 * j], l1 = g_lam[2 * j + 1];
    float4 h = ((const float4*)g_hinitf)[(size_t)c * 128 + j];
    const uint2* base = (const uint2*)(g_BuH + (size_t)c * CHUNK * NW1) + j;
    __half* of = g_hf + (size_t)c * CHUNK * NW1 + 4 * j;
    #pragma unroll 8
    for (int t = 0; t < CHUNK; t++) {
        uint2 u = base[(size_t)t * 128];
        __half2 b0 = *(__half2*)&u.x;
        __half2 b1 = *(__half2*)&u.y;
        float nr0 = fmaf(l0.x, h.x, fmaf(-l0.y, h.y, __low2float(b0)));
        float ni0 = fmaf(l0.x, h.y, fmaf( l0.y, h.x, __high2float(b0)));
        float nr1 = fmaf(l1.x, h.z, fmaf(-l1.y, h.w, __low2float(b1)));
        float ni1 = fmaf(l1.x, h.w, fmaf( l1.y, h.z, __high2float(b1)));
        h = make_float4(nr0, ni0, nr1, ni1);
        __half2 p0 = __floats2half2_rn(nr0, ni0);
        __half2 p1 = __floats2half2_rn(nr1, ni1);
        uint2 o;
        o.x = *reinterpret_cast<uint32_t*>(&p0);
        o.y = *reinterpret_cast<uint32_t*>(&p1);
        *reinterpret_cast<uint2*>(of + (size_t)t * NW1) = o;
    }
}

// ---------------- entry ----------------
extern "C" void kernel_launch(void* const* d_in, const int* in_sizes, int n_in,
                              void* d_out, int out_size) {
    const float* x         = (const float*)d_in[0];
    const float* nu_log    = (const float*)d_in[1];
    const float* theta_log = (const float*)d_in[2];
    const float* gamma_log = (const float*)d_in[3];
    const float* B_re      = (const float*)d_in[4];
    const float* B_im      = (const float*)d_in[5];
    const float* C_re      = (const float*)d_in[6];
    const float* C_im      = (const float*)d_in[7];
    const float* Dv        = (const float*)d_in[8];
    float* y = (float*)d_out;

    cudaFuncSetAttribute(gemm1_k, cudaFuncAttributeMaxDynamicSharedMemorySize, SMEM_G);
    cudaFuncSetAttribute(gemm2_k, cudaFuncAttributeMaxDynamicSharedMemorySize, SMEM_G);

    setup_params<<<1, 256>>>(nu_log, theta_log);
    setup_weights<<<512, 256>>>(gamma_log, B_re, B_im, C_re, C_im);
    cvt_x<<<(L_SEQ * DM / 4) / 256, 256>>>(x);

    // GEMM1 (+ fused per-chunk carry scan): BuH = x @ W1T^T
    gemm1_k<<<dim3(NW1 / 128, L_SEQ / 128), 256, SMEM_G>>>();

    chunk_prefix_ks<<<128, NCHUNK>>>();
    scan_apply<<<NCHUNK, 128>>>();

    // GEMM2: y = h @ W2T^T + x*D
    gemm2_k<<<dim3(DM / 128, L_SEQ / 128), 256, SMEM_G>>>(y, x, Dv);
}